// round 4
// baseline (speedup 1.0000x reference)
#include <cuda_runtime.h>
#include <math.h>

// Problem constants
#define BB 2
#define SS 8192
#define CC 64
#define MMG 32
#define GG (SS / MMG)          // 256 groups per batch
#define BCS (BB * CC * SS)

// Scratch (device globals — allocation-free)
__device__ float g_Pf[BCS];
__device__ float g_Qf[BCS];
__device__ float g_Pe[BCS];
__device__ float g_Qe[BCS];
__device__ float g_Ef[BCS];
__device__ float g_Eg[BCS];
__device__ float g_F1[BCS];
__device__ float g_agg[BCS];

typedef unsigned long long u64;

// ---------------------------------------------------------------------------
// packed fp32 helpers (Blackwell f32x2)
// ---------------------------------------------------------------------------
__device__ __forceinline__ void ffma2(u64& d, u64 a, u64 b) {
    asm("fma.rn.f32x2 %0, %1, %2, %0;" : "+l"(d) : "l"(a), "l"(b));
}
__device__ __forceinline__ u64 add2(u64 a, u64 b) {
    u64 r; asm("add.rn.f32x2 %0, %1, %2;" : "=l"(r) : "l"(a), "l"(b)); return r;
}
__device__ __forceinline__ u64 splat2(float a) {
    u64 r; asm("mov.b64 %0, {%1, %1};" : "=l"(r) : "f"(a)); return r;
}
__device__ __forceinline__ float2 unpack2(u64 v) {
    float2 r; asm("mov.b64 {%0, %1}, %2;" : "=f"(r.x), "=f"(r.y) : "l"(v)); return r;
}
__device__ __forceinline__ u64 ld64s(const float* p) {
    return *reinterpret_cast<const u64*>(p);
}
// two interleaved butterfly sums (sm_100 has no redux.f32)
__device__ __forceinline__ float2 warp_rsum2(float a, float b) {
#pragma unroll
    for (int o = 16; o > 0; o >>= 1) {
        a += __shfl_xor_sync(0xffffffffu, a, o);
        b += __shfl_xor_sync(0xffffffffu, b, o);
    }
    return make_float2(a, b);
}

// Warp-private matmul: acc[cp] += sum_k Wp[k][2cp..2cp+1] * act[k][lane]
// Wp: [64][64] transposed weights (row k contiguous, broadcast loads)
// act: [64][32] per-warp activations, lane-private column
__device__ __forceinline__ void mm_warp(u64 acc[32], const float* __restrict__ Wp,
                                        const float* __restrict__ act, int lane) {
#pragma unroll 4
    for (int k = 0; k < 64; k++) {
        u64 a = splat2(act[k * 32 + lane]);
        const ulonglong2* wr = reinterpret_cast<const ulonglong2*>(Wp + k * 64);
#pragma unroll
        for (int q = 0; q < 16; q++) {
            ulonglong2 w = wr[q];
            ffma2(acc[2 * q], w.x, a);
            ffma2(acc[2 * q + 1], w.y, a);
        }
    }
}

__device__ __forceinline__ void relu_store(const u64 acc[32], float* __restrict__ dst, int lane) {
#pragma unroll
    for (int cp = 0; cp < 32; cp++) {
        float2 v = unpack2(acc[cp]);
        dst[(2 * cp) * 32 + lane] = fmaxf(v.x, 0.f);
        dst[(2 * cp + 1) * 32 + lane] = fmaxf(v.y, 0.f);
    }
}

// scalar helper used by kernel A
__device__ __forceinline__ void mm64_acc(float acc[8], const float* __restrict__ sW,
                                         int wstride, int cbase,
                                         const float* __restrict__ sA, int lane) {
#pragma unroll 4
    for (int q = 0; q < 16; q++) {
        float a0 = sA[(4 * q + 0) * 32 + lane];
        float a1 = sA[(4 * q + 1) * 32 + lane];
        float a2 = sA[(4 * q + 2) * 32 + lane];
        float a3 = sA[(4 * q + 3) * 32 + lane];
#pragma unroll
        for (int i = 0; i < 8; i++) {
            float4 w = *reinterpret_cast<const float4*>(&sW[(cbase + i) * wstride + 4 * q]);
            acc[i] = fmaf(w.x, a0, acc[i]);
            acc[i] = fmaf(w.y, a1, acc[i]);
            acc[i] = fmaf(w.z, a2, acc[i]);
            acc[i] = fmaf(w.w, a3, acc[i]);
        }
    }
}

// ---------------------------------------------------------------------------
// Kernel A: per-point linear projections (decomposed layer-0 parts)
// ---------------------------------------------------------------------------
struct SmemA {
    float Wpf[64 * 64];
    float Wqf[64 * 64];
    float Wf1[64 * 64];
    float W1x[64 * 8];
    float Wex[64 * 8];
    float W2x[64 * 8];
    float F1t[64 * 32];
    float F2t[64 * 32];
    float X1[3 * 32];
    float X2[3 * 32];
};

__global__ void kernelA(const float* __restrict__ xyz1, const float* __restrict__ feat1,
                        const float* __restrict__ xyz2, const float* __restrict__ feat2,
                        const float* __restrict__ w10, const float* __restrict__ b10,
                        const float* __restrict__ wx1, const float* __restrict__ bx1,
                        const float* __restrict__ wx2, const float* __restrict__ bx2,
                        const float* __restrict__ w30, const float* __restrict__ b30) {
    extern __shared__ float smem_raw[];
    SmemA& s = *reinterpret_cast<SmemA*>(smem_raw);
    int tid = threadIdx.x;
    int t = blockIdx.x;
    int b = t >> 8;
    int s0 = (t & 255) * 32;

    for (int idx = tid; idx < 4096; idx += 256) {
        int c = idx >> 6, j = idx & 63;
        s.Wpf[idx] = w10[c * 138 + 10 + j];
        s.Wqf[idx] = w10[c * 138 + 74 + j];
        s.Wf1[idx] = w30[c * 192 + 64 + j];
    }
    for (int idx = tid; idx < 384; idx += 256) {
        int c = idx / 6, j = idx % 6;
        s.W1x[c * 8 + j] = w10[c * 138 + j];
        s.Wex[c * 8 + j] = wx1[c * 10 + j];
        s.W2x[c * 8 + j] = wx2[c * 10 + j];
    }
    for (int idx = tid; idx < 2048; idx += 256) {
        int c = idx >> 5, k = idx & 31;
        s.F1t[idx] = feat1[b * CC * SS + c * SS + s0 + k];
        s.F2t[idx] = feat2[b * CC * SS + c * SS + s0 + k];
    }
    for (int idx = tid; idx < 96; idx += 256) {
        int i = idx >> 5, k = idx & 31;
        s.X1[idx] = xyz1[b * 3 * SS + i * SS + s0 + k];
        s.X2[idx] = xyz2[b * 3 * SS + i * SS + s0 + k];
    }
    __syncthreads();

    int lane = tid & 31;
    int cb = (tid >> 5) * 8;
    float x10 = s.X1[lane], x11 = s.X1[32 + lane], x12 = s.X1[64 + lane];
    float x20 = s.X2[lane], x21 = s.X2[32 + lane], x22 = s.X2[64 + lane];

    float accPf[8], accQf[8], accF1[8];
#pragma unroll
    for (int i = 0; i < 8; i++) {
        accPf[i] = __ldg(&b10[cb + i]);
        accQf[i] = 0.f;
        accF1[i] = __ldg(&b30[cb + i]);
    }
    mm64_acc(accPf, s.Wpf, 64, cb, s.F1t, lane);
    mm64_acc(accF1, s.Wf1, 64, cb, s.F1t, lane);
    mm64_acc(accQf, s.Wqf, 64, cb, s.F2t, lane);

#pragma unroll
    for (int i = 0; i < 8; i++) {
        int c = cb + i;
        long base = (long)b * CC * SS + (long)c * SS + s0 + lane;
        float pf = accPf[i] + s.W1x[c * 8 + 0] * x10 + s.W1x[c * 8 + 1] * x11 + s.W1x[c * 8 + 2] * x12;
        float qf = accQf[i] + s.W1x[c * 8 + 3] * x20 + s.W1x[c * 8 + 4] * x21 + s.W1x[c * 8 + 5] * x22;
        g_Pf[base] = pf;
        g_Qf[base] = qf;
        g_F1[base] = accF1[i];
        g_Pe[base] = __ldg(&bx1[c]) + s.Wex[c * 8 + 0] * x10 + s.Wex[c * 8 + 1] * x11 + s.Wex[c * 8 + 2] * x12;
        g_Qe[base] = s.Wex[c * 8 + 3] * x20 + s.Wex[c * 8 + 4] * x21 + s.Wex[c * 8 + 5] * x22;
        g_Ef[base] = __ldg(&bx2[c]) + s.W2x[c * 8 + 0] * x10 + s.W2x[c * 8 + 1] * x11 + s.W2x[c * 8 + 2] * x12;
        g_Eg[base] = s.W2x[c * 8 + 3] * x10 + s.W2x[c * 8 + 4] * x11 + s.W2x[c * 8 + 5] * x12;
    }
}

// ---------------------------------------------------------------------------
// Kernel B: stage 1 — warp-private s-points, zero intra-loop barriers
// grid = BB*GG*2 (half-groups), 256 threads; warp w handles s-points {2w, 2w+1}
// ---------------------------------------------------------------------------
struct SmemB {
    float W11p[64 * 64];   // [k][c] transposed
    float W20p[128 * 64];
    float W21p[64 * 64];
    float Qf_t[32 * 68];   // [j][c], padded
    float Qe_t[32 * 68];
    float Pf_h[16 * 64];   // [sl][c] for this half-block's s-points
    float Pe_h[16 * 64];
    float W1dp[4 * 64];    // [t][c], t = d0,d1,d2,euc weights of W1_0[:,6:10]
    float Wedp[4 * 64];
    float B11p[64], B20p[64], B21p[64];
    float X1h[3 * 16];     // s-point coords (xyz1)
    float X2g[3 * 32];     // neighbor coords (xyz2)
    float Outb[64 * 16];
    float bufs[8][2][64 * 32];  // per-warp double buffers (128 KB)
};

__global__ void __launch_bounds__(256, 1)
kernelB(const float* __restrict__ xyz1, const float* __restrict__ xyz2,
        const float* __restrict__ w10, const float* __restrict__ wx1,
        const float* __restrict__ w11, const float* __restrict__ b11,
        const float* __restrict__ w20, const float* __restrict__ b20,
        const float* __restrict__ w21, const float* __restrict__ b21) {
    extern __shared__ float smem_raw[];
    SmemB& s = *reinterpret_cast<SmemB*>(smem_raw);
    int tid = threadIdx.x;
    int bid = blockIdx.x;
    int b = bid >> 9;
    int g = (bid >> 1) & 255;
    int half = bid & 1;
    int sb = g * MMG;
    int sbh = sb + half * 16;
    long cbase = (long)b * CC * SS;

    // weights (transposed for broadcast pair loads)
    for (int idx = tid; idx < 4096; idx += 256) {
        int c = idx >> 6, k = idx & 63;
        s.W11p[k * 64 + c] = w11[idx];
        s.W21p[k * 64 + c] = w21[idx];
    }
    for (int idx = tid; idx < 8192; idx += 256) {
        int c = idx >> 7, k = idx & 127;
        s.W20p[k * 64 + c] = w20[idx];
    }
    // per-point projections
    for (int idx = tid; idx < 2048; idx += 256) {
        int c = idx >> 5, j = idx & 31;
        s.Qf_t[j * 68 + c] = g_Qf[cbase + (long)c * SS + sb + j];
        s.Qe_t[j * 68 + c] = g_Qe[cbase + (long)c * SS + sb + j];
    }
    for (int idx = tid; idx < 1024; idx += 256) {
        int c = idx >> 4, sl = idx & 15;
        s.Pf_h[sl * 64 + c] = g_Pf[cbase + (long)c * SS + sbh + sl];
        s.Pe_h[sl * 64 + c] = g_Pe[cbase + (long)c * SS + sbh + sl];
    }
    if (tid < 256) {
        int t4 = tid >> 6, c = tid & 63;
        s.W1dp[t4 * 64 + c] = w10[c * 138 + 6 + t4];
        s.Wedp[t4 * 64 + c] = wx1[c * 10 + 6 + t4];
    }
    if (tid < 64) {
        s.B11p[tid] = b11[tid];
        s.B20p[tid] = b20[tid];
        s.B21p[tid] = b21[tid];
    }
    if (tid < 48) {
        int d = tid >> 4, sl = tid & 15;
        s.X1h[d * 16 + sl] = xyz1[b * 3 * SS + d * SS + sbh + sl];
    }
    if (tid >= 64 && tid < 160) {
        int i = tid - 64;
        int d = i >> 5, j = i & 31;
        s.X2g[d * 32 + j] = xyz2[b * 3 * SS + d * SS + sb + j];
    }
    __syncthreads();

    int lane = tid & 31;
    int wid = tid >> 5;
    float* buf0 = &s.bufs[wid][0][0];
    float* buf1 = &s.bufs[wid][1][0];

    float nx0 = s.X2g[lane], nx1 = s.X2g[32 + lane], nx2 = s.X2g[64 + lane];

    for (int t = 0; t < 2; t++) {
        int sl = wid * 2 + t;
        float px0 = s.X1h[sl], px1 = s.X1h[16 + sl], px2 = s.X1h[32 + sl];
        float d0 = nx0 - px0, d1 = nx1 - px1, d2 = nx2 - px2;
        float euc = sqrtf(d0 * d0 + d1 * d1 + d2 * d2 + 1e-20f);
        u64 sd0 = splat2(d0), sd1 = splat2(d1), sd2 = splat2(d2), sd3 = splat2(euc);

        // --- H = relu(Pf[sl] + Qf[j] + W1d . [d, euc]) -> buf0 ---
#pragma unroll 8
        for (int cp = 0; cp < 32; cp++) {
            u64 h = add2(ld64s(&s.Pf_h[sl * 64 + 2 * cp]), ld64s(&s.Qf_t[lane * 68 + 2 * cp]));
            ffma2(h, ld64s(&s.W1dp[0 * 64 + 2 * cp]), sd0);
            ffma2(h, ld64s(&s.W1dp[1 * 64 + 2 * cp]), sd1);
            ffma2(h, ld64s(&s.W1dp[2 * 64 + 2 * cp]), sd2);
            ffma2(h, ld64s(&s.W1dp[3 * 64 + 2 * cp]), sd3);
            float2 v = unpack2(h);
            buf0[(2 * cp) * 32 + lane] = fmaxf(v.x, 0.f);
            buf0[(2 * cp + 1) * 32 + lane] = fmaxf(v.y, 0.f);
        }

        // --- PN = relu(W11 @ H + b11) -> buf1 ---
        u64 acc[32];
#pragma unroll
        for (int cp = 0; cp < 32; cp++) acc[cp] = ld64s(&s.B11p[2 * cp]);
        mm_warp(acc, s.W11p, buf0, lane);
        relu_store(acc, buf1, lane);

        // --- PE = relu(Pe[sl] + Qe[j] + Wed . [d, euc]) -> buf0 ---
#pragma unroll 8
        for (int cp = 0; cp < 32; cp++) {
            u64 h = add2(ld64s(&s.Pe_h[sl * 64 + 2 * cp]), ld64s(&s.Qe_t[lane * 68 + 2 * cp]));
            ffma2(h, ld64s(&s.Wedp[0 * 64 + 2 * cp]), sd0);
            ffma2(h, ld64s(&s.Wedp[1 * 64 + 2 * cp]), sd1);
            ffma2(h, ld64s(&s.Wedp[2 * 64 + 2 * cp]), sd2);
            ffma2(h, ld64s(&s.Wedp[3 * 64 + 2 * cp]), sd3);
            float2 v = unpack2(h);
            buf0[(2 * cp) * 32 + lane] = fmaxf(v.x, 0.f);
            buf0[(2 * cp + 1) * 32 + lane] = fmaxf(v.y, 0.f);
        }

        // --- U = relu(W20 @ [PE; PN] + b20) -> buf0 (after reads) ---
#pragma unroll
        for (int cp = 0; cp < 32; cp++) acc[cp] = ld64s(&s.B20p[2 * cp]);
        mm_warp(acc, s.W20p, buf0, lane);            // PE part (rows 0..63)
        mm_warp(acc, s.W20p + 64 * 64, buf1, lane);  // PN part (rows 64..127)
        relu_store(acc, buf0, lane);

        // --- logits = relu(W21 @ U + b21) ---
#pragma unroll
        for (int cp = 0; cp < 32; cp++) acc[cp] = ld64s(&s.B21p[2 * cp]);
        mm_warp(acc, s.W21p, buf0, lane);

        // --- softmax over lanes (j) + aggregate PN ---
#pragma unroll 4
        for (int cp = 0; cp < 32; cp++) {
            float2 l = unpack2(acc[cp]);
            float e0 = __expf(fmaxf(l.x, 0.f));
            float e1 = __expf(fmaxf(l.y, 0.f));
            float p0 = buf1[(2 * cp) * 32 + lane];
            float p1 = buf1[(2 * cp + 1) * 32 + lane];
            float2 r0 = warp_rsum2(e0, e0 * p0);
            float2 r1 = warp_rsum2(e1, e1 * p1);
            if (lane == 0) {
                s.Outb[(2 * cp) * 16 + sl] = r0.y / r0.x;
                s.Outb[(2 * cp + 1) * 16 + sl] = r1.y / r1.x;
            }
        }
    }
    __syncthreads();

    // coalesced flush
    for (int idx = tid; idx < 1024; idx += 256) {
        int c = idx >> 4, sl = idx & 15;
        g_agg[cbase + (long)c * SS + sbh + sl] = s.Outb[c * 16 + sl];
    }
}

// ---------------------------------------------------------------------------
// Kernel C: stage 2 — warp-private s-points; hoisted G = W30b @ pi_agg
// grid = BB*GG*2, 256 threads
// ---------------------------------------------------------------------------
struct SmemC {
    float W30ap[64 * 64];
    float W30bp[64 * 64];
    float W31p[64 * 64];
    float Eg_t[32 * 68];
    float G_t[32 * 68];
    float PAG[64 * 32];
    float Ef_h[16 * 64];
    float F1_h[16 * 64];
    float W2dp[4 * 64];
    float B31p[64];
    float X1g[3 * 32];
    float Outb[64 * 16];
    float bufs[8][2][64 * 32];
};

__global__ void __launch_bounds__(256, 1)
kernelC(const float* __restrict__ xyz1, const float* __restrict__ wx2,
        const float* __restrict__ w30, const float* __restrict__ w31,
        const float* __restrict__ b31, float* __restrict__ out) {
    extern __shared__ float smem_raw[];
    SmemC& s = *reinterpret_cast<SmemC*>(smem_raw);
    int tid = threadIdx.x;
    int bid = blockIdx.x;
    int b = bid >> 9;
    int g = (bid >> 1) & 255;
    int half = bid & 1;
    int sb = g * MMG;
    int sbh = sb + half * 16;
    long cbase = (long)b * CC * SS;

    for (int idx = tid; idx < 4096; idx += 256) {
        int c = idx >> 6, k = idx & 63;
        s.W30ap[k * 64 + c] = w30[c * 192 + k];
        s.W30bp[k * 64 + c] = w30[c * 192 + 128 + k];
        s.W31p[k * 64 + c] = w31[c * 64 + k];
    }
    for (int idx = tid; idx < 2048; idx += 256) {
        int c = idx >> 5, j = idx & 31;
        s.Eg_t[j * 68 + c] = g_Eg[cbase + (long)c * SS + sb + j];
        s.PAG[c * 32 + j] = g_agg[cbase + (long)c * SS + sb + j];
    }
    for (int idx = tid; idx < 1024; idx += 256) {
        int c = idx >> 4, sl = idx & 15;
        s.Ef_h[sl * 64 + c] = g_Ef[cbase + (long)c * SS + sbh + sl];
        s.F1_h[sl * 64 + c] = g_F1[cbase + (long)c * SS + sbh + sl];
    }
    if (tid < 256) {
        int t4 = tid >> 6, c = tid & 63;
        s.W2dp[t4 * 64 + c] = wx2[c * 10 + 6 + t4];
    }
    if (tid < 64) s.B31p[tid] = b31[tid];
    if (tid >= 64 && tid < 160) {
        int i = tid - 64;
        int d = i >> 5, j = i & 31;
        s.X1g[d * 32 + j] = xyz1[b * 3 * SS + d * SS + sb + j];
    }
    __syncthreads();

    int lane = tid & 31;
    int wid = tid >> 5;
    float* buf0 = &s.bufs[wid][0][0];
    float* buf1 = &s.bufs[wid][1][0];

    // --- G = W30b @ pi_agg (s-independent, cooperative: warp wid -> 8 channels) ---
    {
        int cb = wid * 8;
        u64 gacc[4] = {0ull, 0ull, 0ull, 0ull};
#pragma unroll 4
        for (int k = 0; k < 64; k++) {
            u64 a = splat2(s.PAG[k * 32 + lane]);
            const ulonglong2* wr = reinterpret_cast<const ulonglong2*>(s.W30bp + k * 64 + cb);
            ulonglong2 w0 = wr[0], w1 = wr[1];
            ffma2(gacc[0], w0.x, a);
            ffma2(gacc[1], w0.y, a);
            ffma2(gacc[2], w1.x, a);
            ffma2(gacc[3], w1.y, a);
        }
#pragma unroll
        for (int i = 0; i < 4; i++) {
            float2 v = unpack2(gacc[i]);
            s.G_t[lane * 68 + cb + 2 * i] = v.x;
            s.G_t[lane * 68 + cb + 2 * i + 1] = v.y;
        }
    }
    __syncthreads();

    float nx0 = s.X1g[lane], nx1 = s.X1g[32 + lane], nx2 = s.X1g[64 + lane];

    for (int t = 0; t < 2; t++) {
        int sl = wid * 2 + t;
        int slg = half * 16 + sl;   // position within the 32-group = masked lane
        float px0 = s.X1g[slg], px1 = s.X1g[32 + slg], px2 = s.X1g[64 + slg];
        float d0 = nx0 - px0, d1 = nx1 - px1, d2 = nx2 - px2;
        float euc = sqrtf(d0 * d0 + d1 * d1 + d2 * d2 + 1e-20f);
        u64 sd0 = splat2(d0), sd1 = splat2(d1), sd2 = splat2(d2), sd3 = splat2(euc);

        // --- PE = relu(Ef[sl] + Eg[j] + W2d . [d, euc]) -> buf0 ---
#pragma unroll 8
        for (int cp = 0; cp < 32; cp++) {
            u64 h = add2(ld64s(&s.Ef_h[sl * 64 + 2 * cp]), ld64s(&s.Eg_t[lane * 68 + 2 * cp]));
            ffma2(h, ld64s(&s.W2dp[0 * 64 + 2 * cp]), sd0);
            ffma2(h, ld64s(&s.W2dp[1 * 64 + 2 * cp]), sd1);
            ffma2(h, ld64s(&s.W2dp[2 * 64 + 2 * cp]), sd2);
            ffma2(h, ld64s(&s.W2dp[3 * 64 + 2 * cp]), sd3);
            float2 v = unpack2(h);
            buf0[(2 * cp) * 32 + lane] = fmaxf(v.x, 0.f);
            buf0[(2 * cp + 1) * 32 + lane] = fmaxf(v.y, 0.f);
        }

        // --- T = relu(G + F1[sl] + W30a @ PE) -> buf1 ---
        u64 acc[32];
#pragma unroll
        for (int cp = 0; cp < 32; cp++)
            acc[cp] = add2(ld64s(&s.G_t[lane * 68 + 2 * cp]), ld64s(&s.F1_h[sl * 64 + 2 * cp]));
        mm_warp(acc, s.W30ap, buf0, lane);
        relu_store(acc, buf1, lane);

        // --- logits = relu(W31 @ T + b31) ---
#pragma unroll
        for (int cp = 0; cp < 32; cp++) acc[cp] = ld64s(&s.B31p[2 * cp]);
        mm_warp(acc, s.W31p, buf1, lane);

        // --- masked softmax over lanes (exclude self) + aggregate PAG ---
#pragma unroll 4
        for (int cp = 0; cp < 32; cp++) {
            float2 l = unpack2(acc[cp]);
            float e0 = (lane == slg) ? 0.f : __expf(fmaxf(l.x, 0.f));
            float e1 = (lane == slg) ? 0.f : __expf(fmaxf(l.y, 0.f));
            float p0 = s.PAG[(2 * cp) * 32 + lane];
            float p1 = s.PAG[(2 * cp + 1) * 32 + lane];
            float2 r0 = warp_rsum2(e0, e0 * p0);
            float2 r1 = warp_rsum2(e1, e1 * p1);
            if (lane == 0) {
                s.Outb[(2 * cp) * 16 + sl] = r0.y / r0.x;
                s.Outb[(2 * cp + 1) * 16 + sl] = r1.y / r1.x;
            }
        }
    }
    __syncthreads();

    for (int idx = tid; idx < 1024; idx += 256) {
        int c = idx >> 4, sl = idx & 15;
        out[cbase + (long)c * SS + sbh + sl] = s.Outb[c * 16 + sl];
    }
}

// ---------------------------------------------------------------------------
extern "C" void kernel_launch(void* const* d_in, const int* in_sizes, int n_in,
                              void* d_out, int out_size) {
    const float* xyz1 = (const float*)d_in[0];
    const float* feat1 = (const float*)d_in[1];
    const float* xyz2 = (const float*)d_in[2];
    const float* feat2 = (const float*)d_in[3];
    const float* w10 = (const float*)d_in[4];
    const float* b10 = (const float*)d_in[5];
    const float* w11 = (const float*)d_in[6];
    const float* b11 = (const float*)d_in[7];
    const float* wx1 = (const float*)d_in[8];
    const float* bx1 = (const float*)d_in[9];
    const float* wx2 = (const float*)d_in[10];
    const float* bx2 = (const float*)d_in[11];
    const float* w20 = (const float*)d_in[12];
    const float* b20 = (const float*)d_in[13];
    const float* w21 = (const float*)d_in[14];
    const float* b21 = (const float*)d_in[15];
    const float* w30 = (const float*)d_in[16];
    const float* b30 = (const float*)d_in[17];
    const float* w31 = (const float*)d_in[18];
    const float* b31 = (const float*)d_in[19];
    float* out = (float*)d_out;

    cudaFuncSetAttribute(kernelA, cudaFuncAttributeMaxDynamicSharedMemorySize, (int)sizeof(SmemA));
    cudaFuncSetAttribute(kernelB, cudaFuncAttributeMaxDynamicSharedMemorySize, (int)sizeof(SmemB));
    cudaFuncSetAttribute(kernelC, cudaFuncAttributeMaxDynamicSharedMemorySize, (int)sizeof(SmemC));

    kernelA<<<(BB * SS) / 32, 256, sizeof(SmemA)>>>(xyz1, feat1, xyz2, feat2,
                                                    w10, b10, wx1, bx1, wx2, bx2, w30, b30);
    kernelB<<<BB * GG * 2, 256, sizeof(SmemB)>>>(xyz1, xyz2, w10, wx1,
                                                 w11, b11, w20, b20, w21, b21);
    kernelC<<<BB * GG * 2, 256, sizeof(SmemC)>>>(xyz1, wx2, w30, w31, b31, out);
}

// round 5
// speedup vs baseline: 1.5498x; 1.5498x over previous
#include <cuda_runtime.h>
#include <math.h>

// Problem constants
#define BB 2
#define SS 8192
#define CC 64
#define MMG 32
#define GG (SS / MMG)          // 256 groups per batch
#define BCS (BB * CC * SS)
#define QST 66                 // stride for lane-indexed [j][c] arrays (2-way conflict, 8B-aligned)

// Scratch (device globals — allocation-free)
__device__ float g_Pf[BCS];
__device__ float g_Qf[BCS];
__device__ float g_Pe[BCS];
__device__ float g_Qe[BCS];
__device__ float g_Ef[BCS];
__device__ float g_Eg[BCS];
__device__ float g_F1[BCS];
__device__ float g_agg[BCS];

typedef unsigned long long u64;

// ---------------------------------------------------------------------------
// packed fp32 helpers (Blackwell f32x2)
// ---------------------------------------------------------------------------
__device__ __forceinline__ void ffma2(u64& d, u64 a, u64 b) {
    asm("fma.rn.f32x2 %0, %1, %2, %0;" : "+l"(d) : "l"(a), "l"(b));
}
__device__ __forceinline__ u64 add2(u64 a, u64 b) {
    u64 r; asm("add.rn.f32x2 %0, %1, %2;" : "=l"(r) : "l"(a), "l"(b)); return r;
}
__device__ __forceinline__ u64 splat2(float a) {
    u64 r; asm("mov.b64 %0, {%1, %1};" : "=l"(r) : "f"(a)); return r;
}
__device__ __forceinline__ float2 unpack2(u64 v) {
    float2 r; asm("mov.b64 {%0, %1}, %2;" : "=f"(r.x), "=f"(r.y) : "l"(v)); return r;
}
__device__ __forceinline__ u64 ld64s(const float* p) {
    return *reinterpret_cast<const u64*>(p);
}
// two interleaved butterfly sums (sm_100 has no redux.f32)
__device__ __forceinline__ float2 warp_rsum2(float a, float b) {
#pragma unroll
    for (int o = 16; o > 0; o >>= 1) {
        a += __shfl_xor_sync(0xffffffffu, a, o);
        b += __shfl_xor_sync(0xffffffffu, b, o);
    }
    return make_float2(a, b);
}

// Per-warp matmul slice: 4 channels (2 pairs) at c4, two s-points.
// Wp: [64][64] transposed weights ([k][c], broadcast row loads)
// actA/actB: [64][32] dup-packed activations ({a,a} u64 per (k, lane))
__device__ __forceinline__ void mm4(u64 a0[2], u64 a1[2], const float* __restrict__ Wp,
                                    int c4, const u64* __restrict__ actA,
                                    const u64* __restrict__ actB, int lane) {
    const float* wp = Wp + c4;
    const u64* pa = actA + lane;
    const u64* pb = actB + lane;
#pragma unroll 8
    for (int k = 0; k < 64; k++) {
        ulonglong2 w = *reinterpret_cast<const ulonglong2*>(wp + k * 64);
        u64 aa = pa[k * 32];
        u64 ab = pb[k * 32];
        ffma2(a0[0], w.x, aa); ffma2(a0[1], w.y, aa);
        ffma2(a1[0], w.x, ab); ffma2(a1[1], w.y, ab);
    }
}

// store 2 channel-pairs as dup-packed relu'd activations
__device__ __forceinline__ void relu_store_dup(const u64 a[2], u64* __restrict__ dst,
                                               int c4, int lane) {
#pragma unroll
    for (int pp = 0; pp < 2; pp++) {
        float2 v = unpack2(a[pp]);
        dst[(c4 + 2 * pp) * 32 + lane] = splat2(fmaxf(v.x, 0.f));
        dst[(c4 + 2 * pp + 1) * 32 + lane] = splat2(fmaxf(v.y, 0.f));
    }
}

// scalar helper used by kernel A
__device__ __forceinline__ void mm64_acc(float acc[8], const float* __restrict__ sW,
                                         int wstride, int cbase,
                                         const float* __restrict__ sA, int lane) {
#pragma unroll 4
    for (int q = 0; q < 16; q++) {
        float a0 = sA[(4 * q + 0) * 32 + lane];
        float a1 = sA[(4 * q + 1) * 32 + lane];
        float a2 = sA[(4 * q + 2) * 32 + lane];
        float a3 = sA[(4 * q + 3) * 32 + lane];
#pragma unroll
        for (int i = 0; i < 8; i++) {
            float4 w = *reinterpret_cast<const float4*>(&sW[(cbase + i) * wstride + 4 * q]);
            acc[i] = fmaf(w.x, a0, acc[i]);
            acc[i] = fmaf(w.y, a1, acc[i]);
            acc[i] = fmaf(w.z, a2, acc[i]);
            acc[i] = fmaf(w.w, a3, acc[i]);
        }
    }
}

// ---------------------------------------------------------------------------
// Kernel A: per-point linear projections (decomposed layer-0 parts) — unchanged
// ---------------------------------------------------------------------------
struct SmemA {
    float Wpf[64 * 64];
    float Wqf[64 * 64];
    float Wf1[64 * 64];
    float W1x[64 * 8];
    float Wex[64 * 8];
    float W2x[64 * 8];
    float F1t[64 * 32];
    float F2t[64 * 32];
    float X1[3 * 32];
    float X2[3 * 32];
};

__global__ void kernelA(const float* __restrict__ xyz1, const float* __restrict__ feat1,
                        const float* __restrict__ xyz2, const float* __restrict__ feat2,
                        const float* __restrict__ w10, const float* __restrict__ b10,
                        const float* __restrict__ wx1, const float* __restrict__ bx1,
                        const float* __restrict__ wx2, const float* __restrict__ bx2,
                        const float* __restrict__ w30, const float* __restrict__ b30) {
    extern __shared__ float smem_raw[];
    SmemA& s = *reinterpret_cast<SmemA*>(smem_raw);
    int tid = threadIdx.x;
    int t = blockIdx.x;
    int b = t >> 8;
    int s0 = (t & 255) * 32;

    for (int idx = tid; idx < 4096; idx += 256) {
        int c = idx >> 6, j = idx & 63;
        s.Wpf[idx] = w10[c * 138 + 10 + j];
        s.Wqf[idx] = w10[c * 138 + 74 + j];
        s.Wf1[idx] = w30[c * 192 + 64 + j];
    }
    for (int idx = tid; idx < 384; idx += 256) {
        int c = idx / 6, j = idx % 6;
        s.W1x[c * 8 + j] = w10[c * 138 + j];
        s.Wex[c * 8 + j] = wx1[c * 10 + j];
        s.W2x[c * 8 + j] = wx2[c * 10 + j];
    }
    for (int idx = tid; idx < 2048; idx += 256) {
        int c = idx >> 5, k = idx & 31;
        s.F1t[idx] = feat1[b * CC * SS + c * SS + s0 + k];
        s.F2t[idx] = feat2[b * CC * SS + c * SS + s0 + k];
    }
    for (int idx = tid; idx < 96; idx += 256) {
        int i = idx >> 5, k = idx & 31;
        s.X1[idx] = xyz1[b * 3 * SS + i * SS + s0 + k];
        s.X2[idx] = xyz2[b * 3 * SS + i * SS + s0 + k];
    }
    __syncthreads();

    int lane = tid & 31;
    int cb = (tid >> 5) * 8;
    float x10 = s.X1[lane], x11 = s.X1[32 + lane], x12 = s.X1[64 + lane];
    float x20 = s.X2[lane], x21 = s.X2[32 + lane], x22 = s.X2[64 + lane];

    float accPf[8], accQf[8], accF1[8];
#pragma unroll
    for (int i = 0; i < 8; i++) {
        accPf[i] = __ldg(&b10[cb + i]);
        accQf[i] = 0.f;
        accF1[i] = __ldg(&b30[cb + i]);
    }
    mm64_acc(accPf, s.Wpf, 64, cb, s.F1t, lane);
    mm64_acc(accF1, s.Wf1, 64, cb, s.F1t, lane);
    mm64_acc(accQf, s.Wqf, 64, cb, s.F2t, lane);

#pragma unroll
    for (int i = 0; i < 8; i++) {
        int c = cb + i;
        long base = (long)b * CC * SS + (long)c * SS + s0 + lane;
        float pf = accPf[i] + s.W1x[c * 8 + 0] * x10 + s.W1x[c * 8 + 1] * x11 + s.W1x[c * 8 + 2] * x12;
        float qf = accQf[i] + s.W1x[c * 8 + 3] * x20 + s.W1x[c * 8 + 4] * x21 + s.W1x[c * 8 + 5] * x22;
        g_Pf[base] = pf;
        g_Qf[base] = qf;
        g_F1[base] = accF1[i];
        g_Pe[base] = __ldg(&bx1[c]) + s.Wex[c * 8 + 0] * x10 + s.Wex[c * 8 + 1] * x11 + s.Wex[c * 8 + 2] * x12;
        g_Qe[base] = s.Wex[c * 8 + 3] * x20 + s.Wex[c * 8 + 4] * x21 + s.Wex[c * 8 + 5] * x22;
        g_Ef[base] = __ldg(&bx2[c]) + s.W2x[c * 8 + 0] * x10 + s.W2x[c * 8 + 1] * x11 + s.W2x[c * 8 + 2] * x12;
        g_Eg[base] = s.W2x[c * 8 + 3] * x10 + s.W2x[c * 8 + 4] * x11 + s.W2x[c * 8 + 5] * x12;
    }
}

// ---------------------------------------------------------------------------
// Kernel B: stage 1 — 512 threads, 16 warps x 4 channels, 2 s-points per pass
// grid = BB*GG*2 (half-groups)
// ---------------------------------------------------------------------------
struct SmemB {
    u64 Ha[64 * 32], Hb[64 * 32];      // dup-packed activations
    u64 PEa[64 * 32], PEb[64 * 32];
    u64 PNa[64 * 32], PNb[64 * 32];
    float W11p[64 * 64];               // [k][c] transposed
    float W20p[128 * 64];
    float W21p[64 * 64];
    float Qf_t[32 * QST], Qe_t[32 * QST];   // [j][c]
    float Pf_h[16 * 64], Pe_h[16 * 64];     // [sl][c]
    float W1dp[4 * 64], Wedp[4 * 64];       // [t][c]
    float B11p[64], B20p[64], B21p[64];
    float X1h[3 * 16];
    float X2g[3 * 32];
    float Outb[64 * 16];
};

__global__ void __launch_bounds__(512, 1)
kernelB(const float* __restrict__ xyz1, const float* __restrict__ xyz2,
        const float* __restrict__ w10, const float* __restrict__ wx1,
        const float* __restrict__ w11, const float* __restrict__ b11,
        const float* __restrict__ w20, const float* __restrict__ b20,
        const float* __restrict__ w21, const float* __restrict__ b21) {
    extern __shared__ float smem_raw[];
    SmemB& s = *reinterpret_cast<SmemB*>(smem_raw);
    int tid = threadIdx.x;
    int bid = blockIdx.x;
    int b = bid >> 9;
    int g = (bid >> 1) & 255;
    int half = bid & 1;
    int sb = g * MMG;
    int sbh = sb + half * 16;
    long cbase = (long)b * CC * SS;

    for (int idx = tid; idx < 4096; idx += 512) {
        int c = idx >> 6, k = idx & 63;
        s.W11p[k * 64 + c] = w11[idx];
        s.W21p[k * 64 + c] = w21[idx];
    }
    for (int idx = tid; idx < 8192; idx += 512) {
        int c = idx >> 7, k = idx & 127;
        s.W20p[k * 64 + c] = w20[idx];
    }
    for (int idx = tid; idx < 2048; idx += 512) {
        int c = idx >> 5, j = idx & 31;
        s.Qf_t[j * QST + c] = g_Qf[cbase + (long)c * SS + sb + j];
        s.Qe_t[j * QST + c] = g_Qe[cbase + (long)c * SS + sb + j];
    }
    for (int idx = tid; idx < 1024; idx += 512) {
        int c = idx >> 4, sl = idx & 15;
        s.Pf_h[sl * 64 + c] = g_Pf[cbase + (long)c * SS + sbh + sl];
        s.Pe_h[sl * 64 + c] = g_Pe[cbase + (long)c * SS + sbh + sl];
    }
    if (tid < 256) {
        int t4 = tid >> 6, c = tid & 63;
        s.W1dp[t4 * 64 + c] = w10[c * 138 + 6 + t4];
        s.Wedp[t4 * 64 + c] = wx1[c * 10 + 6 + t4];
    }
    if (tid < 64) {
        s.B11p[tid] = b11[tid];
        s.B20p[tid] = b20[tid];
        s.B21p[tid] = b21[tid];
    }
    if (tid >= 448 && tid < 496) {
        int i = tid - 448;
        int d = i >> 4, sl = i & 15;
        s.X1h[d * 16 + sl] = xyz1[b * 3 * SS + d * SS + sbh + sl];
    }
    if (tid >= 320 && tid < 416) {
        int i = tid - 320;
        int d = i >> 5, j = i & 31;
        s.X2g[d * 32 + j] = xyz2[b * 3 * SS + d * SS + sb + j];
    }
    __syncthreads();

    int lane = tid & 31;
    int wid = tid >> 5;
    int c4 = wid * 4;

    float nx0 = s.X2g[lane], nx1 = s.X2g[32 + lane], nx2 = s.X2g[64 + lane];

    for (int p = 0; p < 8; p++) {
        int sl0 = 2 * p, sl1 = 2 * p + 1;

        // --- step 1: H and PE (dynamic parts) for both s -> dup buffers ---
        {
            float pa0 = s.X1h[sl0], pa1 = s.X1h[16 + sl0], pa2 = s.X1h[32 + sl0];
            float pb0 = s.X1h[sl1], pb1 = s.X1h[16 + sl1], pb2 = s.X1h[32 + sl1];
            float da0 = nx0 - pa0, da1 = nx1 - pa1, da2 = nx2 - pa2;
            float db0 = nx0 - pb0, db1 = nx1 - pb1, db2 = nx2 - pb2;
            float ea = sqrtf(da0 * da0 + da1 * da1 + da2 * da2 + 1e-20f);
            float eb = sqrtf(db0 * db0 + db1 * db1 + db2 * db2 + 1e-20f);
            u64 A0 = splat2(da0), A1 = splat2(da1), A2 = splat2(da2), A3 = splat2(ea);
            u64 B0 = splat2(db0), B1 = splat2(db1), B2 = splat2(db2), B3 = splat2(eb);
#pragma unroll
            for (int pp = 0; pp < 2; pp++) {
                int c = c4 + 2 * pp;
                u64 w0 = ld64s(&s.W1dp[0 * 64 + c]), w1 = ld64s(&s.W1dp[1 * 64 + c]);
                u64 w2 = ld64s(&s.W1dp[2 * 64 + c]), w3 = ld64s(&s.W1dp[3 * 64 + c]);
                u64 qf = ld64s(&s.Qf_t[lane * QST + c]);
                u64 ha = add2(ld64s(&s.Pf_h[sl0 * 64 + c]), qf);
                u64 hb = add2(ld64s(&s.Pf_h[sl1 * 64 + c]), qf);
                ffma2(ha, w0, A0); ffma2(ha, w1, A1); ffma2(ha, w2, A2); ffma2(ha, w3, A3);
                ffma2(hb, w0, B0); ffma2(hb, w1, B1); ffma2(hb, w2, B2); ffma2(hb, w3, B3);
                float2 va = unpack2(ha), vb = unpack2(hb);
                s.Ha[c * 32 + lane] = splat2(fmaxf(va.x, 0.f));
                s.Ha[(c + 1) * 32 + lane] = splat2(fmaxf(va.y, 0.f));
                s.Hb[c * 32 + lane] = splat2(fmaxf(vb.x, 0.f));
                s.Hb[(c + 1) * 32 + lane] = splat2(fmaxf(vb.y, 0.f));

                u64 v0 = ld64s(&s.Wedp[0 * 64 + c]), v1 = ld64s(&s.Wedp[1 * 64 + c]);
                u64 v2 = ld64s(&s.Wedp[2 * 64 + c]), v3 = ld64s(&s.Wedp[3 * 64 + c]);
                u64 qe = ld64s(&s.Qe_t[lane * QST + c]);
                u64 pea = add2(ld64s(&s.Pe_h[sl0 * 64 + c]), qe);
                u64 peb = add2(ld64s(&s.Pe_h[sl1 * 64 + c]), qe);
                ffma2(pea, v0, A0); ffma2(pea, v1, A1); ffma2(pea, v2, A2); ffma2(pea, v3, A3);
                ffma2(peb, v0, B0); ffma2(peb, v1, B1); ffma2(peb, v2, B2); ffma2(peb, v3, B3);
                float2 ua = unpack2(pea), ub = unpack2(peb);
                s.PEa[c * 32 + lane] = splat2(fmaxf(ua.x, 0.f));
                s.PEa[(c + 1) * 32 + lane] = splat2(fmaxf(ua.y, 0.f));
                s.PEb[c * 32 + lane] = splat2(fmaxf(ub.x, 0.f));
                s.PEb[(c + 1) * 32 + lane] = splat2(fmaxf(ub.y, 0.f));
            }
        }
        __syncthreads();

        // --- step 2: PN = relu(W11 @ H + b11) ---
        u64 a0[2], a1[2];
        {
            u64 bv0 = ld64s(&s.B11p[c4]), bv1 = ld64s(&s.B11p[c4 + 2]);
            a0[0] = bv0; a0[1] = bv1; a1[0] = bv0; a1[1] = bv1;
        }
        mm4(a0, a1, s.W11p, c4, s.Ha, s.Hb, lane);
        relu_store_dup(a0, s.PNa, c4, lane);
        relu_store_dup(a1, s.PNb, c4, lane);
        __syncthreads();

        // --- step 3: U = relu(W20 @ [PE; PN] + b20) -> overwrite H buffers ---
        {
            u64 bv0 = ld64s(&s.B20p[c4]), bv1 = ld64s(&s.B20p[c4 + 2]);
            a0[0] = bv0; a0[1] = bv1; a1[0] = bv0; a1[1] = bv1;
        }
        mm4(a0, a1, s.W20p, c4, s.PEa, s.PEb, lane);
        mm4(a0, a1, s.W20p + 64 * 64, c4, s.PNa, s.PNb, lane);
        relu_store_dup(a0, s.Ha, c4, lane);
        relu_store_dup(a1, s.Hb, c4, lane);
        __syncthreads();

        // --- step 4: logits = relu(W21 @ U + b21); softmax over lanes; aggregate ---
        {
            u64 bv0 = ld64s(&s.B21p[c4]), bv1 = ld64s(&s.B21p[c4 + 2]);
            a0[0] = bv0; a0[1] = bv1; a1[0] = bv0; a1[1] = bv1;
        }
        mm4(a0, a1, s.W21p, c4, s.Ha, s.Hb, lane);

        const float* pna = reinterpret_cast<const float*>(s.PNa);
        const float* pnb = reinterpret_cast<const float*>(s.PNb);
#pragma unroll
        for (int pp = 0; pp < 2; pp++) {
            int c0 = c4 + 2 * pp, c1 = c0 + 1;
            float2 la = unpack2(a0[pp]), lb = unpack2(a1[pp]);
            float e00 = __expf(fmaxf(la.x, 0.f));
            float e01 = __expf(fmaxf(la.y, 0.f));
            float e10 = __expf(fmaxf(lb.x, 0.f));
            float e11 = __expf(fmaxf(lb.y, 0.f));
            float p00 = pna[(c0 * 32 + lane) * 2];
            float p01 = pna[(c1 * 32 + lane) * 2];
            float p10 = pnb[(c0 * 32 + lane) * 2];
            float p11 = pnb[(c1 * 32 + lane) * 2];
            float2 r00 = warp_rsum2(e00, e00 * p00);
            float2 r01 = warp_rsum2(e01, e01 * p01);
            float2 r10 = warp_rsum2(e10, e10 * p10);
            float2 r11 = warp_rsum2(e11, e11 * p11);
            if (lane == 0) {
                s.Outb[c0 * 16 + sl0] = r00.y / r00.x;
                s.Outb[c1 * 16 + sl0] = r01.y / r01.x;
                s.Outb[c0 * 16 + sl1] = r10.y / r10.x;
                s.Outb[c1 * 16 + sl1] = r11.y / r11.x;
            }
        }
        __syncthreads();
    }

    // coalesced flush
    for (int idx = tid; idx < 1024; idx += 512) {
        int c = idx >> 4, sl = idx & 15;
        g_agg[cbase + (long)c * SS + sbh + sl] = s.Outb[c * 16 + sl];
    }
}

// ---------------------------------------------------------------------------
// Kernel C: stage 2 — 512 threads, 16 warps x 4 channels; hoisted G = W30b@pi_agg
// grid = BB*GG*2
// ---------------------------------------------------------------------------
struct SmemC {
    u64 PAGd[64 * 32];
    u64 PEa[64 * 32], PEb[64 * 32];
    u64 Ta[64 * 32], Tb[64 * 32];
    float W30ap[64 * 64];
    float W30bp[64 * 64];
    float W31p[64 * 64];
    float Eg_t[32 * QST];
    float G_t[32 * QST];
    float Ef_h[16 * 64], F1_h[16 * 64];
    float W2dp[4 * 64];
    float B31p[64];
    float X1g[3 * 32];
    float Outb[64 * 16];
};

__global__ void __launch_bounds__(512, 1)
kernelC(const float* __restrict__ xyz1, const float* __restrict__ wx2,
        const float* __restrict__ w30, const float* __restrict__ w31,
        const float* __restrict__ b31, float* __restrict__ out) {
    extern __shared__ float smem_raw[];
    SmemC& s = *reinterpret_cast<SmemC*>(smem_raw);
    int tid = threadIdx.x;
    int bid = blockIdx.x;
    int b = bid >> 9;
    int g = (bid >> 1) & 255;
    int half = bid & 1;
    int sb = g * MMG;
    int sbh = sb + half * 16;
    long cbase = (long)b * CC * SS;

    for (int idx = tid; idx < 4096; idx += 512) {
        int c = idx >> 6, k = idx & 63;
        s.W30ap[k * 64 + c] = w30[c * 192 + k];
        s.W30bp[k * 64 + c] = w30[c * 192 + 128 + k];
        s.W31p[k * 64 + c] = w31[c * 64 + k];
    }
    for (int idx = tid; idx < 2048; idx += 512) {
        int c = idx >> 5, j = idx & 31;
        s.Eg_t[j * QST + c] = g_Eg[cbase + (long)c * SS + sb + j];
        s.PAGd[c * 32 + j] = splat2(g_agg[cbase + (long)c * SS + sb + j]);
    }
    for (int idx = tid; idx < 1024; idx += 512) {
        int c = idx >> 4, sl = idx & 15;
        s.Ef_h[sl * 64 + c] = g_Ef[cbase + (long)c * SS + sbh + sl];
        s.F1_h[sl * 64 + c] = g_F1[cbase + (long)c * SS + sbh + sl];
    }
    if (tid < 256) {
        int t4 = tid >> 6, c = tid & 63;
        s.W2dp[t4 * 64 + c] = wx2[c * 10 + 6 + t4];
    }
    if (tid < 64) s.B31p[tid] = b31[tid];
    if (tid >= 320 && tid < 416) {
        int i = tid - 320;
        int d = i >> 5, j = i & 31;
        s.X1g[d * 32 + j] = xyz1[b * 3 * SS + d * SS + sb + j];
    }
    __syncthreads();

    int lane = tid & 31;
    int wid = tid >> 5;
    int c4 = wid * 4;

    // --- G = W30b @ pi_agg (s-independent): warp computes its 4 channels ---
    {
        u64 gacc[2] = {0ull, 0ull};
        const float* wp = s.W30bp + c4;
        const u64* pa = s.PAGd + lane;
#pragma unroll 8
        for (int k = 0; k < 64; k++) {
            ulonglong2 w = *reinterpret_cast<const ulonglong2*>(wp + k * 64);
            u64 a = pa[k * 32];
            ffma2(gacc[0], w.x, a);
            ffma2(gacc[1], w.y, a);
        }
        float2 v0 = unpack2(gacc[0]), v1 = unpack2(gacc[1]);
        s.G_t[lane * QST + c4 + 0] = v0.x;
        s.G_t[lane * QST + c4 + 1] = v0.y;
        s.G_t[lane * QST + c4 + 2] = v1.x;
        s.G_t[lane * QST + c4 + 3] = v1.y;
    }
    __syncthreads();

    float nx0 = s.X1g[lane], nx1 = s.X1g[32 + lane], nx2 = s.X1g[64 + lane];

    for (int p = 0; p < 8; p++) {
        int sl0 = 2 * p, sl1 = 2 * p + 1;
        int sg0 = half * 16 + sl0, sg1 = half * 16 + sl1;

        // --- step 1: PE = relu(Ef[sl] + Eg[j] + W2d . [d, euc]) ---
        {
            float pa0 = s.X1g[sg0], pa1 = s.X1g[32 + sg0], pa2 = s.X1g[64 + sg0];
            float pb0 = s.X1g[sg1], pb1 = s.X1g[32 + sg1], pb2 = s.X1g[64 + sg1];
            float da0 = nx0 - pa0, da1 = nx1 - pa1, da2 = nx2 - pa2;
            float db0 = nx0 - pb0, db1 = nx1 - pb1, db2 = nx2 - pb2;
            float ea = sqrtf(da0 * da0 + da1 * da1 + da2 * da2 + 1e-20f);
            float eb = sqrtf(db0 * db0 + db1 * db1 + db2 * db2 + 1e-20f);
            u64 A0 = splat2(da0), A1 = splat2(da1), A2 = splat2(da2), A3 = splat2(ea);
            u64 B0 = splat2(db0), B1 = splat2(db1), B2 = splat2(db2), B3 = splat2(eb);
#pragma unroll
            for (int pp = 0; pp < 2; pp++) {
                int c = c4 + 2 * pp;
                u64 w0 = ld64s(&s.W2dp[0 * 64 + c]), w1 = ld64s(&s.W2dp[1 * 64 + c]);
                u64 w2 = ld64s(&s.W2dp[2 * 64 + c]), w3 = ld64s(&s.W2dp[3 * 64 + c]);
                u64 eg = ld64s(&s.Eg_t[lane * QST + c]);
                u64 va = add2(ld64s(&s.Ef_h[sl0 * 64 + c]), eg);
                u64 vb = add2(ld64s(&s.Ef_h[sl1 * 64 + c]), eg);
                ffma2(va, w0, A0); ffma2(va, w1, A1); ffma2(va, w2, A2); ffma2(va, w3, A3);
                ffma2(vb, w0, B0); ffma2(vb, w1, B1); ffma2(vb, w2, B2); ffma2(vb, w3, B3);
                float2 ua = unpack2(va), ub = unpack2(vb);
                s.PEa[c * 32 + lane] = splat2(fmaxf(ua.x, 0.f));
                s.PEa[(c + 1) * 32 + lane] = splat2(fmaxf(ua.y, 0.f));
                s.PEb[c * 32 + lane] = splat2(fmaxf(ub.x, 0.f));
                s.PEb[(c + 1) * 32 + lane] = splat2(fmaxf(ub.y, 0.f));
            }
        }
        __syncthreads();

        // --- step 2: T = relu(G + F1[sl] + W30a @ PE) ---
        u64 a0[2], a1[2];
        {
            u64 g0 = ld64s(&s.G_t[lane * QST + c4]);
            u64 g1 = ld64s(&s.G_t[lane * QST + c4 + 2]);
            a0[0] = add2(g0, ld64s(&s.F1_h[sl0 * 64 + c4]));
            a0[1] = add2(g1, ld64s(&s.F1_h[sl0 * 64 + c4 + 2]));
            a1[0] = add2(g0, ld64s(&s.F1_h[sl1 * 64 + c4]));
            a1[1] = add2(g1, ld64s(&s.F1_h[sl1 * 64 + c4 + 2]));
        }
        mm4(a0, a1, s.W30ap, c4, s.PEa, s.PEb, lane);
        relu_store_dup(a0, s.Ta, c4, lane);
        relu_store_dup(a1, s.Tb, c4, lane);
        __syncthreads();

        // --- step 3: logits = relu(W31 @ T + b31); masked softmax; aggregate ---
        {
            u64 bv0 = ld64s(&s.B31p[c4]), bv1 = ld64s(&s.B31p[c4 + 2]);
            a0[0] = bv0; a0[1] = bv1; a1[0] = bv0; a1[1] = bv1;
        }
        mm4(a0, a1, s.W31p, c4, s.Ta, s.Tb, lane);

        const float* pag = reinterpret_cast<const float*>(s.PAGd);
#pragma unroll
        for (int pp = 0; pp < 2; pp++) {
            int c0 = c4 + 2 * pp, c1 = c0 + 1;
            float2 la = unpack2(a0[pp]), lb = unpack2(a1[pp]);
            float e00 = (lane == sg0) ? 0.f : __expf(fmaxf(la.x, 0.f));
            float e01 = (lane == sg0) ? 0.f : __expf(fmaxf(la.y, 0.f));
            float e10 = (lane == sg1) ? 0.f : __expf(fmaxf(lb.x, 0.f));
            float e11 = (lane == sg1) ? 0.f : __expf(fmaxf(lb.y, 0.f));
            float p0 = pag[(c0 * 32 + lane) * 2];
            float p1 = pag[(c1 * 32 + lane) * 2];
            float2 r00 = warp_rsum2(e00, e00 * p0);
            float2 r01 = warp_rsum2(e01, e01 * p1);
            float2 r10 = warp_rsum2(e10, e10 * p0);
            float2 r11 = warp_rsum2(e11, e11 * p1);
            if (lane == 0) {
                s.Outb[c0 * 16 + sl0] = r00.y / r00.x;
                s.Outb[c1 * 16 + sl0] = r01.y / r01.x;
                s.Outb[c0 * 16 + sl1] = r10.y / r10.x;
                s.Outb[c1 * 16 + sl1] = r11.y / r11.x;
            }
        }
        __syncthreads();
    }

    for (int idx = tid; idx < 1024; idx += 512) {
        int c = idx >> 4, sl = idx & 15;
        out[cbase + (long)c * SS + sbh + sl] = s.Outb[c * 16 + sl];
    }
}

// ---------------------------------------------------------------------------
extern "C" void kernel_launch(void* const* d_in, const int* in_sizes, int n_in,
                              void* d_out, int out_size) {
    const float* xyz1 = (const float*)d_in[0];
    const float* feat1 = (const float*)d_in[1];
    const float* xyz2 = (const float*)d_in[2];
    const float* feat2 = (const float*)d_in[3];
    const float* w10 = (const float*)d_in[4];
    const float* b10 = (const float*)d_in[5];
    const float* w11 = (const float*)d_in[6];
    const float* b11 = (const float*)d_in[7];
    const float* wx1 = (const float*)d_in[8];
    const float* bx1 = (const float*)d_in[9];
    const float* wx2 = (const float*)d_in[10];
    const float* bx2 = (const float*)d_in[11];
    const float* w20 = (const float*)d_in[12];
    const float* b20 = (const float*)d_in[13];
    const float* w21 = (const float*)d_in[14];
    const float* b21 = (const float*)d_in[15];
    const float* w30 = (const float*)d_in[16];
    const float* b30 = (const float*)d_in[17];
    const float* w31 = (const float*)d_in[18];
    const float* b31 = (const float*)d_in[19];
    float* out = (float*)d_out;

    cudaFuncSetAttribute(kernelA, cudaFuncAttributeMaxDynamicSharedMemorySize, (int)sizeof(SmemA));
    cudaFuncSetAttribute(kernelB, cudaFuncAttributeMaxDynamicSharedMemorySize, (int)sizeof(SmemB));
    cudaFuncSetAttribute(kernelC, cudaFuncAttributeMaxDynamicSharedMemorySize, (int)sizeof(SmemC));

    kernelA<<<(BB * SS) / 32, 256, sizeof(SmemA)>>>(xyz1, feat1, xyz2, feat2,
                                                    w10, b10, wx1, bx1, wx2, bx2, w30, b30);
    kernelB<<<BB * GG * 2, 512, sizeof(SmemB)>>>(xyz1, xyz2, w10, wx1,
                                                 w11, b11, w20, b20, w21, b21);
    kernelC<<<BB * GG * 2, 512, sizeof(SmemC)>>>(xyz1, wx2, w30, w31, b31, out);
}

// round 7
// speedup vs baseline: 2.4144x; 1.5579x over previous
#include <cuda_runtime.h>
#include <math.h>

// Problem constants
#define BB 2
#define SS 8192
#define CC 64
#define MMG 32
#define GG (SS / MMG)          // 256 groups per batch
#define BCS (BB * CC * SS)
#define WST 64                 // weight row stride ([k][c] layout; broadcast loads, no padding needed)

// Scratch (device globals — allocation-free)
__device__ float g_Pf[BCS];
__device__ float g_Qf[BCS];
__device__ float g_Pe[BCS];
__device__ float g_Qe[BCS];
__device__ float g_Ef[BCS];
__device__ float g_Eg[BCS];
__device__ float g_F1[BCS];
__device__ float g_agg[BCS];

typedef unsigned long long u64;

// ---------------------------------------------------------------------------
// packed fp32 helpers (Blackwell f32x2) + warp reduction
// ---------------------------------------------------------------------------
__device__ __forceinline__ void ffma2(u64& d, u64 a, u64 b) {
    asm("fma.rn.f32x2 %0, %1, %2, %0;" : "+l"(d) : "l"(a), "l"(b));
}
__device__ __forceinline__ u64 splat2(float a) {
    u64 r; asm("mov.b64 %0, {%1, %1};" : "=l"(r) : "f"(a)); return r;
}
__device__ __forceinline__ u64 pack2(float x, float y) {
    u64 r; asm("mov.b64 %0, {%1, %2};" : "=l"(r) : "f"(x), "f"(y)); return r;
}
__device__ __forceinline__ float2 unpack2(u64 v) {
    float2 r; asm("mov.b64 {%0, %1}, %2;" : "=f"(r.x), "=f"(r.y) : "l"(v)); return r;
}
// two interleaved butterfly sums (sm_100 has no redux.f32)
__device__ __forceinline__ float2 warp_rsum2(float a, float b) {
#pragma unroll
    for (int o = 16; o > 0; o >>= 1) {
        a += __shfl_xor_sync(0xffffffffu, a, o);
        b += __shfl_xor_sync(0xffffffffu, b, o);
    }
    return make_float2(a, b);
}

// Packed matmul over K=64: acc{0,1}[i] += Wt[k][cb+2i..] * A{0,1}[k][lane]
// Wt: [k][c] transposed weights, row stride WST (broadcast pair loads)
__device__ __forceinline__ void mmT2(u64 acc0[4], u64 acc1[4],
                                     const float* __restrict__ sWt, int cb,
                                     const float* __restrict__ sA0,
                                     const float* __restrict__ sA1, int lane) {
#pragma unroll 8
    for (int k = 0; k < 64; k++) {
        ulonglong2 wlo = *reinterpret_cast<const ulonglong2*>(sWt + k * WST + cb);
        ulonglong2 whi = *reinterpret_cast<const ulonglong2*>(sWt + k * WST + cb + 4);
        u64 a0 = splat2(sA0[k * 32 + lane]);
        u64 a1 = splat2(sA1[k * 32 + lane]);
        ffma2(acc0[0], wlo.x, a0); ffma2(acc0[1], wlo.y, a0);
        ffma2(acc0[2], whi.x, a0); ffma2(acc0[3], whi.y, a0);
        ffma2(acc1[0], wlo.x, a1); ffma2(acc1[1], wlo.y, a1);
        ffma2(acc1[2], whi.x, a1); ffma2(acc1[3], whi.y, a1);
    }
}

// scalar helper used by kernel A
__device__ __forceinline__ void mm64_acc(float acc[8], const float* __restrict__ sW,
                                         int wstride, int cbase,
                                         const float* __restrict__ sA, int lane) {
#pragma unroll 4
    for (int q = 0; q < 16; q++) {
        float a0 = sA[(4 * q + 0) * 32 + lane];
        float a1 = sA[(4 * q + 1) * 32 + lane];
        float a2 = sA[(4 * q + 2) * 32 + lane];
        float a3 = sA[(4 * q + 3) * 32 + lane];
#pragma unroll
        for (int i = 0; i < 8; i++) {
            float4 w = *reinterpret_cast<const float4*>(&sW[(cbase + i) * wstride + 4 * q]);
            acc[i] = fmaf(w.x, a0, acc[i]);
            acc[i] = fmaf(w.y, a1, acc[i]);
            acc[i] = fmaf(w.z, a2, acc[i]);
            acc[i] = fmaf(w.w, a3, acc[i]);
        }
    }
}

// ---------------------------------------------------------------------------
// Kernel A: per-point linear projections (decomposed layer-0 parts) — unchanged
// ---------------------------------------------------------------------------
struct SmemA {
    float Wpf[64 * 64];
    float Wqf[64 * 64];
    float Wf1[64 * 64];
    float W1x[64 * 8];
    float Wex[64 * 8];
    float W2x[64 * 8];
    float F1t[64 * 32];
    float F2t[64 * 32];
    float X1[3 * 32];
    float X2[3 * 32];
};

__global__ void kernelA(const float* __restrict__ xyz1, const float* __restrict__ feat1,
                        const float* __restrict__ xyz2, const float* __restrict__ feat2,
                        const float* __restrict__ w10, const float* __restrict__ b10,
                        const float* __restrict__ wx1, const float* __restrict__ bx1,
                        const float* __restrict__ wx2, const float* __restrict__ bx2,
                        const float* __restrict__ w30, const float* __restrict__ b30) {
    extern __shared__ float smem_raw[];
    SmemA& s = *reinterpret_cast<SmemA*>(smem_raw);
    int tid = threadIdx.x;
    int t = blockIdx.x;
    int b = t >> 8;
    int s0 = (t & 255) * 32;

    for (int idx = tid; idx < 4096; idx += 256) {
        int c = idx >> 6, j = idx & 63;
        s.Wpf[idx] = w10[c * 138 + 10 + j];
        s.Wqf[idx] = w10[c * 138 + 74 + j];
        s.Wf1[idx] = w30[c * 192 + 64 + j];
    }
    for (int idx = tid; idx < 384; idx += 256) {
        int c = idx / 6, j = idx % 6;
        s.W1x[c * 8 + j] = w10[c * 138 + j];
        s.Wex[c * 8 + j] = wx1[c * 10 + j];
        s.W2x[c * 8 + j] = wx2[c * 10 + j];
    }
    for (int idx = tid; idx < 2048; idx += 256) {
        int c = idx >> 5, k = idx & 31;
        s.F1t[idx] = feat1[b * CC * SS + c * SS + s0 + k];
        s.F2t[idx] = feat2[b * CC * SS + c * SS + s0 + k];
    }
    for (int idx = tid; idx < 96; idx += 256) {
        int i = idx >> 5, k = idx & 31;
        s.X1[idx] = xyz1[b * 3 * SS + i * SS + s0 + k];
        s.X2[idx] = xyz2[b * 3 * SS + i * SS + s0 + k];
    }
    __syncthreads();

    int lane = tid & 31;
    int cb = (tid >> 5) * 8;
    float x10 = s.X1[lane], x11 = s.X1[32 + lane], x12 = s.X1[64 + lane];
    float x20 = s.X2[lane], x21 = s.X2[32 + lane], x22 = s.X2[64 + lane];

    float accPf[8], accQf[8], accF1[8];
#pragma unroll
    for (int i = 0; i < 8; i++) {
        accPf[i] = __ldg(&b10[cb + i]);
        accQf[i] = 0.f;
        accF1[i] = __ldg(&b30[cb + i]);
    }
    mm64_acc(accPf, s.Wpf, 64, cb, s.F1t, lane);
    mm64_acc(accF1, s.Wf1, 64, cb, s.F1t, lane);
    mm64_acc(accQf, s.Wqf, 64, cb, s.F2t, lane);

#pragma unroll
    for (int i = 0; i < 8; i++) {
        int c = cb + i;
        long base = (long)b * CC * SS + (long)c * SS + s0 + lane;
        float pf = accPf[i] + s.W1x[c * 8 + 0] * x10 + s.W1x[c * 8 + 1] * x11 + s.W1x[c * 8 + 2] * x12;
        float qf = accQf[i] + s.W1x[c * 8 + 3] * x20 + s.W1x[c * 8 + 4] * x21 + s.W1x[c * 8 + 5] * x22;
        g_Pf[base] = pf;
        g_Qf[base] = qf;
        g_F1[base] = accF1[i];
        g_Pe[base] = __ldg(&bx1[c]) + s.Wex[c * 8 + 0] * x10 + s.Wex[c * 8 + 1] * x11 + s.Wex[c * 8 + 2] * x12;
        g_Qe[base] = s.Wex[c * 8 + 3] * x20 + s.Wex[c * 8 + 4] * x21 + s.Wex[c * 8 + 5] * x22;
        g_Ef[base] = __ldg(&bx2[c]) + s.W2x[c * 8 + 0] * x10 + s.W2x[c * 8 + 1] * x11 + s.W2x[c * 8 + 2] * x12;
        g_Eg[base] = s.W2x[c * 8 + 3] * x10 + s.W2x[c * 8 + 4] * x11 + s.W2x[c * 8 + 5] * x12;
    }
}

// ---------------------------------------------------------------------------
// Kernel B: stage 1 — R3 structure x2 teams; 512 threads, 16 warps (2 teams x 8)
// grid = BB*GG*2 (half-groups); team t handles s-pair (4p+2t, 4p+2t+1), 4 passes
// ---------------------------------------------------------------------------
struct SmemB {
    float W11t[64 * WST];
    float W20t[128 * WST];
    float W21t[64 * WST];
    float W1d[64 * 4];
    float Wed[64 * 4];
    float B11[64], B20[64], B21[64];
    float Pf[64 * 32], Pe[64 * 32];
    float X1[3 * 32], X2[3 * 32];
    float Ha[2][64 * 32], Hb[2][64 * 32];
    float PEa[2][64 * 32], PEb[2][64 * 32];
    float PNa[2][64 * 32], PNb[2][64 * 32];
};

__global__ void __launch_bounds__(512, 1)
kernelB(const float* __restrict__ xyz1, const float* __restrict__ xyz2,
        const float* __restrict__ w10, const float* __restrict__ wx1,
        const float* __restrict__ w11, const float* __restrict__ b11,
        const float* __restrict__ w20, const float* __restrict__ b20,
        const float* __restrict__ w21, const float* __restrict__ b21) {
    extern __shared__ float smem_raw[];
    SmemB& s = *reinterpret_cast<SmemB*>(smem_raw);
    int tid = threadIdx.x;
    int bid = blockIdx.x;
    int b = bid >> 9;
    int g = (bid >> 1) & 255;
    int half = bid & 1;
    int sb = g * MMG;
    long cbase = (long)b * CC * SS;

    for (int idx = tid; idx < 4096; idx += 512) {
        int c = idx >> 6, k = idx & 63;
        s.W11t[k * WST + c] = w11[idx];
        s.W21t[k * WST + c] = w21[idx];
    }
    for (int idx = tid; idx < 8192; idx += 512) {
        int c = idx >> 7, k = idx & 127;
        s.W20t[k * WST + c] = w20[idx];
    }
    if (tid < 256) {
        int c = tid >> 2, j = tid & 3;
        s.W1d[tid] = w10[c * 138 + 6 + j];
        s.Wed[tid] = wx1[c * 10 + 6 + j];
    }
    if (tid < 64) {
        s.B11[tid] = b11[tid];
        s.B20[tid] = b20[tid];
        s.B21[tid] = b21[tid];
    }
    for (int idx = tid; idx < 2048; idx += 512) {
        int c = idx >> 5, k = idx & 31;
        long base = cbase + (long)c * SS + sb + k;
        s.Pf[idx] = g_Pf[base];
        s.Pe[idx] = g_Pe[base];
    }
    if (tid >= 384 && tid < 480) {
        int i = tid - 384;
        int d = i >> 5, k = i & 31;
        s.X1[d * 32 + k] = xyz1[b * 3 * SS + d * SS + sb + k];
        s.X2[d * 32 + k] = xyz2[b * 3 * SS + d * SS + sb + k];
    }
    __syncthreads();

    int lane = tid & 31;
    int wid = tid >> 5;
    int team = wid >> 3;
    int cb = (wid & 7) * 8;
    long outbase = cbase + sb;

    float qf[8], qe[8];
#pragma unroll
    for (int i = 0; i < 8; i++) {
        long base = cbase + (long)(cb + i) * SS + sb + lane;
        qf[i] = __ldg(&g_Qf[base]);
        qe[i] = __ldg(&g_Qe[base]);
    }

    float nx0 = s.X2[lane], nx1 = s.X2[32 + lane], nx2 = s.X2[64 + lane];

    float* Ha = s.Ha[team];  float* Hb = s.Hb[team];
    float* PEa = s.PEa[team]; float* PEb = s.PEb[team];
    float* PNa = s.PNa[team]; float* PNb = s.PNb[team];

    for (int p = 0; p < 4; p++) {
        int sl0 = half * 16 + 4 * p + 2 * team;
        int sl1 = sl0 + 1;

        // --- step 1: dynamic parts for both s ---
        {
            float pa0 = s.X1[sl0], pa1 = s.X1[32 + sl0], pa2 = s.X1[64 + sl0];
            float pb0 = s.X1[sl1], pb1 = s.X1[32 + sl1], pb2 = s.X1[64 + sl1];
            float da0 = nx0 - pa0, da1 = nx1 - pa1, da2 = nx2 - pa2;
            float db0 = nx0 - pb0, db1 = nx1 - pb1, db2 = nx2 - pb2;
            float ea = sqrtf(da0 * da0 + da1 * da1 + da2 * da2 + 1e-20f);
            float eb = sqrtf(db0 * db0 + db1 * db1 + db2 * db2 + 1e-20f);
#pragma unroll
            for (int i = 0; i < 8; i++) {
                int c = cb + i;
                float w0 = s.W1d[c * 4 + 0], w1 = s.W1d[c * 4 + 1], w2 = s.W1d[c * 4 + 2], w3 = s.W1d[c * 4 + 3];
                float ha = s.Pf[c * 32 + sl0] + qf[i] + w0 * da0 + w1 * da1 + w2 * da2 + w3 * ea;
                float hb = s.Pf[c * 32 + sl1] + qf[i] + w0 * db0 + w1 * db1 + w2 * db2 + w3 * eb;
                Ha[c * 32 + lane] = fmaxf(ha, 0.f);
                Hb[c * 32 + lane] = fmaxf(hb, 0.f);
                float v0 = s.Wed[c * 4 + 0], v1 = s.Wed[c * 4 + 1], v2 = s.Wed[c * 4 + 2], v3 = s.Wed[c * 4 + 3];
                float pea = s.Pe[c * 32 + sl0] + qe[i] + v0 * da0 + v1 * da1 + v2 * da2 + v3 * ea;
                float peb = s.Pe[c * 32 + sl1] + qe[i] + v0 * db0 + v1 * db1 + v2 * db2 + v3 * eb;
                PEa[c * 32 + lane] = fmaxf(pea, 0.f);
                PEb[c * 32 + lane] = fmaxf(peb, 0.f);
            }
        }
        __syncthreads();

        // --- step 2: pi_new = relu(W1_1 @ H + b1_1) ---
        u64 acc0[4], acc1[4];
#pragma unroll
        for (int i = 0; i < 4; i++) {
            u64 bv = *reinterpret_cast<const u64*>(&s.B11[cb + 2 * i]);
            acc0[i] = bv; acc1[i] = bv;
        }
        mmT2(acc0, acc1, s.W11t, cb, Ha, Hb, lane);
#pragma unroll
        for (int i = 0; i < 4; i++) {
            float2 ra = unpack2(acc0[i]), rb = unpack2(acc1[i]);
            PNa[(cb + 2 * i) * 32 + lane] = fmaxf(ra.x, 0.f);
            PNa[(cb + 2 * i + 1) * 32 + lane] = fmaxf(ra.y, 0.f);
            PNb[(cb + 2 * i) * 32 + lane] = fmaxf(rb.x, 0.f);
            PNb[(cb + 2 * i + 1) * 32 + lane] = fmaxf(rb.y, 0.f);
        }
        __syncthreads();

        // --- step 3: U = relu(W2_0 @ [PE; PN] + b2_0) -> overwrite H ---
#pragma unroll
        for (int i = 0; i < 4; i++) {
            u64 bv = *reinterpret_cast<const u64*>(&s.B20[cb + 2 * i]);
            acc0[i] = bv; acc1[i] = bv;
        }
        mmT2(acc0, acc1, s.W20t, cb, PEa, PEb, lane);
        mmT2(acc0, acc1, s.W20t + 64 * WST, cb, PNa, PNb, lane);
#pragma unroll
        for (int i = 0; i < 4; i++) {
            float2 ra = unpack2(acc0[i]), rb = unpack2(acc1[i]);
            Ha[(cb + 2 * i) * 32 + lane] = fmaxf(ra.x, 0.f);
            Ha[(cb + 2 * i + 1) * 32 + lane] = fmaxf(ra.y, 0.f);
            Hb[(cb + 2 * i) * 32 + lane] = fmaxf(rb.x, 0.f);
            Hb[(cb + 2 * i + 1) * 32 + lane] = fmaxf(rb.y, 0.f);
        }
        __syncthreads();

        // --- step 4: logits = relu(W2_1 @ U + b2_1); softmax; aggregate ---
#pragma unroll
        for (int i = 0; i < 4; i++) {
            u64 bv = *reinterpret_cast<const u64*>(&s.B21[cb + 2 * i]);
            acc0[i] = bv; acc1[i] = bv;
        }
        mmT2(acc0, acc1, s.W21t, cb, Ha, Hb, lane);
#pragma unroll
        for (int i = 0; i < 4; i++) {
            float2 la = unpack2(acc0[i]), lb = unpack2(acc1[i]);
            int c0 = cb + 2 * i, c1 = c0 + 1;
            float pn00 = PNa[c0 * 32 + lane];
            float pn01 = PNa[c1 * 32 + lane];
            float pn10 = PNb[c0 * 32 + lane];
            float pn11 = PNb[c1 * 32 + lane];
            float e00 = __expf(fmaxf(la.x, 0.f));
            float e01 = __expf(fmaxf(la.y, 0.f));
            float e10 = __expf(fmaxf(lb.x, 0.f));
            float e11 = __expf(fmaxf(lb.y, 0.f));
            float2 r00 = warp_rsum2(e00, e00 * pn00);
            float2 r01 = warp_rsum2(e01, e01 * pn01);
            float2 r10 = warp_rsum2(e10, e10 * pn10);
            float2 r11 = warp_rsum2(e11, e11 * pn11);
            if (lane == 0) {
                g_agg[outbase + (long)c0 * SS + sl0] = r00.y / r00.x;
                g_agg[outbase + (long)c1 * SS + sl0] = r01.y / r01.x;
                g_agg[outbase + (long)c0 * SS + sl1] = r10.y / r10.x;
                g_agg[outbase + (long)c1 * SS + sl1] = r11.y / r11.x;
            }
        }
        __syncthreads();
    }
}

// ---------------------------------------------------------------------------
// Kernel C: stage 2 — R3 structure x2 teams; 512 threads; hoisted G = W30b@pi_agg
// grid = BB*GG*2
// ---------------------------------------------------------------------------
struct SmemC {
    float W30at[64 * WST];
    float W30bt[64 * WST];
    float W31t[64 * WST];
    float W2d[64 * 4];
    float B31[64];
    float Ef[64 * 32], Eg[64 * 32], F1[64 * 32], PAG[64 * 32];
    float X1[3 * 32];
    float G[64 * 32];
    float Ta[2][64 * 32], Tb[2][64 * 32];
    float Pa[2][64 * 32], Pb[2][64 * 32];
};

__global__ void __launch_bounds__(512, 1)
kernelC(const float* __restrict__ xyz1, const float* __restrict__ wx2,
        const float* __restrict__ w30, const float* __restrict__ w31,
        const float* __restrict__ b31, float* __restrict__ out) {
    extern __shared__ float smem_raw[];
    SmemC& s = *reinterpret_cast<SmemC*>(smem_raw);
    int tid = threadIdx.x;
    int bid = blockIdx.x;
    int b = bid >> 9;
    int g = (bid >> 1) & 255;
    int half = bid & 1;
    int sb = g * MMG;
    long cbase = (long)b * CC * SS;

    for (int idx = tid; idx < 4096; idx += 512) {
        int c = idx >> 6, k = idx & 63;
        s.W30at[k * WST + c] = w30[c * 192 + k];
        s.W30bt[k * WST + c] = w30[c * 192 + 128 + k];
        s.W31t[k * WST + c] = w31[c * 64 + k];
    }
    if (tid < 256) {
        int c = tid >> 2, j = tid & 3;
        s.W2d[tid] = wx2[c * 10 + 6 + j];
    }
    if (tid < 64) s.B31[tid] = b31[tid];
    for (int idx = tid; idx < 2048; idx += 512) {
        int c = idx >> 5, k = idx & 31;
        long base = cbase + (long)c * SS + sb + k;
        s.Ef[idx] = g_Ef[base];
        s.Eg[idx] = g_Eg[base];
        s.F1[idx] = g_F1[base];
        s.PAG[idx] = g_agg[base];
    }
    if (tid >= 384 && tid < 480) {
        int i = tid - 384;
        int d = i >> 5, k = i & 31;
        s.X1[d * 32 + k] = xyz1[b * 3 * SS + d * SS + sb + k];
    }
    __syncthreads();

    int lane = tid & 31;
    int wid = tid >> 5;
    int team = wid >> 3;
    int cb = (wid & 7) * 8;
    long outbase = cbase + sb;

    // --- G = W30b @ pi_agg (s-independent): 16 warps x 4 channels ---
    {
        int c4 = wid * 4;
        u64 gacc[2] = {0ull, 0ull};
#pragma unroll 8
        for (int k = 0; k < 64; k++) {
            ulonglong2 w = *reinterpret_cast<const ulonglong2*>(s.W30bt + k * WST + c4);
            u64 a = splat2(s.PAG[k * 32 + lane]);
            ffma2(gacc[0], w.x, a);
            ffma2(gacc[1], w.y, a);
        }
        float2 v0 = unpack2(gacc[0]), v1 = unpack2(gacc[1]);
        s.G[(c4 + 0) * 32 + lane] = v0.x;
        s.G[(c4 + 1) * 32 + lane] = v0.y;
        s.G[(c4 + 2) * 32 + lane] = v1.x;
        s.G[(c4 + 3) * 32 + lane] = v1.y;
    }
    __syncthreads();

    float nx0 = s.X1[lane], nx1 = s.X1[32 + lane], nx2 = s.X1[64 + lane];

    float* Pa = s.Pa[team]; float* Pb = s.Pb[team];
    float* Ta = s.Ta[team]; float* Tb = s.Tb[team];

    for (int p = 0; p < 4; p++) {
        int sl0 = half * 16 + 4 * p + 2 * team;
        int sl1 = sl0 + 1;

        // --- step 1: pc_enc for both s ---
        {
            float pa0 = s.X1[sl0], pa1 = s.X1[32 + sl0], pa2 = s.X1[64 + sl0];
            float pb0 = s.X1[sl1], pb1 = s.X1[32 + sl1], pb2 = s.X1[64 + sl1];
            float da0 = nx0 - pa0, da1 = nx1 - pa1, da2 = nx2 - pa2;
            float db0 = nx0 - pb0, db1 = nx1 - pb1, db2 = nx2 - pb2;
            float ea = sqrtf(da0 * da0 + da1 * da1 + da2 * da2 + 1e-20f);
            float eb = sqrtf(db0 * db0 + db1 * db1 + db2 * db2 + 1e-20f);
#pragma unroll
            for (int i = 0; i < 8; i++) {
                int c = cb + i;
                float w0 = s.W2d[c * 4 + 0], w1 = s.W2d[c * 4 + 1], w2 = s.W2d[c * 4 + 2], w3 = s.W2d[c * 4 + 3];
                float base_c = s.Eg[c * 32 + lane];
                float va = s.Ef[c * 32 + sl0] + base_c + w0 * da0 + w1 * da1 + w2 * da2 + w3 * ea;
                float vb = s.Ef[c * 32 + sl1] + base_c + w0 * db0 + w1 * db1 + w2 * db2 + w3 * eb;
                Pa[c * 32 + lane] = fmaxf(va, 0.f);
                Pb[c * 32 + lane] = fmaxf(vb, 0.f);
            }
        }
        __syncthreads();

        // --- step 2: T = relu(G + F1[.,sl] + W3_0a @ pc_enc) ---
        u64 acc0[4], acc1[4];
#pragma unroll
        for (int i = 0; i < 4; i++) {
            int c0 = cb + 2 * i, c1 = c0 + 1;
            float g0 = s.G[c0 * 32 + lane], g1 = s.G[c1 * 32 + lane];
            acc0[i] = pack2(g0 + s.F1[c0 * 32 + sl0], g1 + s.F1[c1 * 32 + sl0]);
            acc1[i] = pack2(g0 + s.F1[c0 * 32 + sl1], g1 + s.F1[c1 * 32 + sl1]);
        }
        mmT2(acc0, acc1, s.W30at, cb, Pa, Pb, lane);
#pragma unroll
        for (int i = 0; i < 4; i++) {
            float2 ra = unpack2(acc0[i]), rb = unpack2(acc1[i]);
            Ta[(cb + 2 * i) * 32 + lane] = fmaxf(ra.x, 0.f);
            Ta[(cb + 2 * i + 1) * 32 + lane] = fmaxf(ra.y, 0.f);
            Tb[(cb + 2 * i) * 32 + lane] = fmaxf(rb.x, 0.f);
            Tb[(cb + 2 * i + 1) * 32 + lane] = fmaxf(rb.y, 0.f);
        }
        __syncthreads();

        // --- step 3: logits = relu(W3_1 @ T + b3_1); masked softmax; aggregate ---
#pragma unroll
        for (int i = 0; i < 4; i++) {
            u64 bv = *reinterpret_cast<const u64*>(&s.B31[cb + 2 * i]);
            acc0[i] = bv; acc1[i] = bv;
        }
        mmT2(acc0, acc1, s.W31t, cb, Ta, Tb, lane);
#pragma unroll
        for (int i = 0; i < 4; i++) {
            float2 la = unpack2(acc0[i]), lb = unpack2(acc1[i]);
            int c0 = cb + 2 * i, c1 = c0 + 1;
            float pg0 = s.PAG[c0 * 32 + lane];
            float pg1 = s.PAG[c1 * 32 + lane];
            float e00 = (lane == sl0) ? 0.f : __expf(fmaxf(la.x, 0.f));
            float e01 = (lane == sl0) ? 0.f : __expf(fmaxf(la.y, 0.f));
            float e10 = (lane == sl1) ? 0.f : __expf(fmaxf(lb.x, 0.f));
            float e11 = (lane == sl1) ? 0.f : __expf(fmaxf(lb.y, 0.f));
            float2 r00 = warp_rsum2(e00, e00 * pg0);
            float2 r01 = warp_rsum2(e01, e01 * pg1);
            float2 r10 = warp_rsum2(e10, e10 * pg0);
            float2 r11 = warp_rsum2(e11, e11 * pg1);
            if (lane == 0) {
                out[outbase + (long)c0 * SS + sl0] = r00.y / r00.x;
                out[outbase + (long)c1 * SS + sl0] = r01.y / r01.x;
                out[outbase + (long)c0 * SS + sl1] = r10.y / r10.x;
                out[outbase + (long)c1 * SS + sl1] = r11.y / r11.x;
            }
        }
        __syncthreads();
    }
}

// ---------------------------------------------------------------------------
extern "C" void kernel_launch(void* const* d_in, const int* in_sizes, int n_in,
                              void* d_out, int out_size) {
    const float* xyz1 = (const float*)d_in[0];
    const float* feat1 = (const float*)d_in[1];
    const float* xyz2 = (const float*)d_in[2];
    const float* feat2 = (const float*)d_in[3];
    const float* w10 = (const float*)d_in[4];
    const float* b10 = (const float*)d_in[5];
    const float* w11 = (const float*)d_in[6];
    const float* b11 = (const float*)d_in[7];
    const float* wx1 = (const float*)d_in[8];
    const float* bx1 = (const float*)d_in[9];
    const float* wx2 = (const float*)d_in[10];
    const float* bx2 = (const float*)d_in[11];
    const float* w20 = (const float*)d_in[12];
    const float* b20 = (const float*)d_in[13];
    const float* w21 = (const float*)d_in[14];
    const float* b21 = (const float*)d_in[15];
    const float* w30 = (const float*)d_in[16];
    const float* b30 = (const float*)d_in[17];
    const float* w31 = (const float*)d_in[18];
    const float* b31 = (const float*)d_in[19];
    float* out = (float*)d_out;

    cudaFuncSetAttribute(kernelA, cudaFuncAttributeMaxDynamicSharedMemorySize, (int)sizeof(SmemA));
    cudaFuncSetAttribute(kernelB, cudaFuncAttributeMaxDynamicSharedMemorySize, (int)sizeof(SmemB));
    cudaFuncSetAttribute(kernelC, cudaFuncAttributeMaxDynamicSharedMemorySize, (int)sizeof(SmemC));

    kernelA<<<(BB * SS) / 32, 256, sizeof(SmemA)>>>(xyz1, feat1, xyz2, feat2,
                                                    w10, b10, wx1, bx1, wx2, bx2, w30, b30);
    kernelB<<<BB * GG * 2, 512, sizeof(SmemB)>>>(xyz1, xyz2, w10, wx1,
                                                 w11, b11, w20, b20, w21, b21);
    kernelC<<<BB * GG * 2, 512, sizeof(SmemC)>>>(xyz1, wx2, w30, w31, b31, out);
}

// round 9
// speedup vs baseline: 2.4765x; 1.0257x over previous
#include <cuda_runtime.h>
#include <math.h>

// Problem constants
#define BB 2
#define SS 8192
#define CC 64
#define MMG 32
#define GG (SS / MMG)          // 256 groups per batch
#define BCS (BB * CC * SS)
#define WST 64                 // weight row stride ([k][c] layout; broadcast loads)

// Scratch (device globals — allocation-free)
__device__ float g_Pf[BCS];
__device__ float g_Qf[BCS];
__device__ float g_Pe[BCS];
__device__ float g_Qe[BCS];
__device__ float g_Ef[BCS];
__device__ float g_Eg[BCS];
__device__ float g_F1[BCS];
__device__ float g_agg[BCS];

typedef unsigned long long u64;

// per-team named barrier: 256 threads of team t sync on barrier id t+1
#define TEAM_BAR(t) asm volatile("bar.sync %0, 256;" :: "r"((t) + 1) : "memory")

// ---------------------------------------------------------------------------
// packed fp32 helpers (Blackwell f32x2) + warp reduction
// ---------------------------------------------------------------------------
__device__ __forceinline__ void ffma2(u64& d, u64 a, u64 b) {
    asm("fma.rn.f32x2 %0, %1, %2, %0;" : "+l"(d) : "l"(a), "l"(b));
}
__device__ __forceinline__ u64 splat2(float a) {
    u64 r; asm("mov.b64 %0, {%1, %1};" : "=l"(r) : "f"(a)); return r;
}
__device__ __forceinline__ u64 pack2(float x, float y) {
    u64 r; asm("mov.b64 %0, {%1, %2};" : "=l"(r) : "f"(x), "f"(y)); return r;
}
__device__ __forceinline__ float2 unpack2(u64 v) {
    float2 r; asm("mov.b64 {%0, %1}, %2;" : "=f"(r.x), "=f"(r.y) : "l"(v)); return r;
}
// two interleaved butterfly sums (sm_100 has no redux.f32)
__device__ __forceinline__ float2 warp_rsum2(float a, float b) {
#pragma unroll
    for (int o = 16; o > 0; o >>= 1) {
        a += __shfl_xor_sync(0xffffffffu, a, o);
        b += __shfl_xor_sync(0xffffffffu, b, o);
    }
    return make_float2(a, b);
}

// Packed matmul over K=64: acc{0,1}[i] += Wt[k][cb+2i..] * A{0,1}[k][lane]
__device__ __forceinline__ void mmT2(u64 acc0[4], u64 acc1[4],
                                     const float* __restrict__ sWt, int cb,
                                     const float* __restrict__ sA0,
                                     const float* __restrict__ sA1, int lane) {
#pragma unroll 8
    for (int k = 0; k < 64; k++) {
        ulonglong2 wlo = *reinterpret_cast<const ulonglong2*>(sWt + k * WST + cb);
        ulonglong2 whi = *reinterpret_cast<const ulonglong2*>(sWt + k * WST + cb + 4);
        u64 a0 = splat2(sA0[k * 32 + lane]);
        u64 a1 = splat2(sA1[k * 32 + lane]);
        ffma2(acc0[0], wlo.x, a0); ffma2(acc0[1], wlo.y, a0);
        ffma2(acc0[2], whi.x, a0); ffma2(acc0[3], whi.y, a0);
        ffma2(acc1[0], wlo.x, a1); ffma2(acc1[1], wlo.y, a1);
        ffma2(acc1[2], whi.x, a1); ffma2(acc1[3], whi.y, a1);
    }
}

// scalar helper used by kernel A
__device__ __forceinline__ void mm64_acc(float acc[8], const float* __restrict__ sW,
                                         int wstride, int cbase,
                                         const float* __restrict__ sA, int lane) {
#pragma unroll 4
    for (int q = 0; q < 16; q++) {
        float a0 = sA[(4 * q + 0) * 32 + lane];
        float a1 = sA[(4 * q + 1) * 32 + lane];
        float a2 = sA[(4 * q + 2) * 32 + lane];
        float a3 = sA[(4 * q + 3) * 32 + lane];
#pragma unroll
        for (int i = 0; i < 8; i++) {
            float4 w = *reinterpret_cast<const float4*>(&sW[(cbase + i) * wstride + 4 * q]);
            acc[i] = fmaf(w.x, a0, acc[i]);
            acc[i] = fmaf(w.y, a1, acc[i]);
            acc[i] = fmaf(w.z, a2, acc[i]);
            acc[i] = fmaf(w.w, a3, acc[i]);
        }
    }
}

// ---------------------------------------------------------------------------
// Kernel A: per-point linear projections (decomposed layer-0 parts) — unchanged
// ---------------------------------------------------------------------------
struct SmemA {
    float Wpf[64 * 64];
    float Wqf[64 * 64];
    float Wf1[64 * 64];
    float W1x[64 * 8];
    float Wex[64 * 8];
    float W2x[64 * 8];
    float F1t[64 * 32];
    float F2t[64 * 32];
    float X1[3 * 32];
    float X2[3 * 32];
};

__global__ void kernelA(const float* __restrict__ xyz1, const float* __restrict__ feat1,
                        const float* __restrict__ xyz2, const float* __restrict__ feat2,
                        const float* __restrict__ w10, const float* __restrict__ b10,
                        const float* __restrict__ wx1, const float* __restrict__ bx1,
                        const float* __restrict__ wx2, const float* __restrict__ bx2,
                        const float* __restrict__ w30, const float* __restrict__ b30) {
    extern __shared__ float smem_raw[];
    SmemA& s = *reinterpret_cast<SmemA*>(smem_raw);
    int tid = threadIdx.x;
    int t = blockIdx.x;
    int b = t >> 8;
    int s0 = (t & 255) * 32;

    for (int idx = tid; idx < 4096; idx += 256) {
        int c = idx >> 6, j = idx & 63;
        s.Wpf[idx] = w10[c * 138 + 10 + j];
        s.Wqf[idx] = w10[c * 138 + 74 + j];
        s.Wf1[idx] = w30[c * 192 + 64 + j];
    }
    for (int idx = tid; idx < 384; idx += 256) {
        int c = idx / 6, j = idx % 6;
        s.W1x[c * 8 + j] = w10[c * 138 + j];
        s.Wex[c * 8 + j] = wx1[c * 10 + j];
        s.W2x[c * 8 + j] = wx2[c * 10 + j];
    }
    for (int idx = tid; idx < 2048; idx += 256) {
        int c = idx >> 5, k = idx & 31;
        s.F1t[idx] = feat1[b * CC * SS + c * SS + s0 + k];
        s.F2t[idx] = feat2[b * CC * SS + c * SS + s0 + k];
    }
    for (int idx = tid; idx < 96; idx += 256) {
        int i = idx >> 5, k = idx & 31;
        s.X1[idx] = xyz1[b * 3 * SS + i * SS + s0 + k];
        s.X2[idx] = xyz2[b * 3 * SS + i * SS + s0 + k];
    }
    __syncthreads();

    int lane = tid & 31;
    int cb = (tid >> 5) * 8;
    float x10 = s.X1[lane], x11 = s.X1[32 + lane], x12 = s.X1[64 + lane];
    float x20 = s.X2[lane], x21 = s.X2[32 + lane], x22 = s.X2[64 + lane];

    float accPf[8], accQf[8], accF1[8];
#pragma unroll
    for (int i = 0; i < 8; i++) {
        accPf[i] = __ldg(&b10[cb + i]);
        accQf[i] = 0.f;
        accF1[i] = __ldg(&b30[cb + i]);
    }
    mm64_acc(accPf, s.Wpf, 64, cb, s.F1t, lane);
    mm64_acc(accF1, s.Wf1, 64, cb, s.F1t, lane);
    mm64_acc(accQf, s.Wqf, 64, cb, s.F2t, lane);

#pragma unroll
    for (int i = 0; i < 8; i++) {
        int c = cb + i;
        long base = (long)b * CC * SS + (long)c * SS + s0 + lane;
        float pf = accPf[i] + s.W1x[c * 8 + 0] * x10 + s.W1x[c * 8 + 1] * x11 + s.W1x[c * 8 + 2] * x12;
        float qf = accQf[i] + s.W1x[c * 8 + 3] * x20 + s.W1x[c * 8 + 4] * x21 + s.W1x[c * 8 + 5] * x22;
        g_Pf[base] = pf;
        g_Qf[base] = qf;
        g_F1[base] = accF1[i];
        g_Pe[base] = __ldg(&bx1[c]) + s.Wex[c * 8 + 0] * x10 + s.Wex[c * 8 + 1] * x11 + s.Wex[c * 8 + 2] * x12;
        g_Qe[base] = s.Wex[c * 8 + 3] * x20 + s.Wex[c * 8 + 4] * x21 + s.Wex[c * 8 + 5] * x22;
        g_Ef[base] = __ldg(&bx2[c]) + s.W2x[c * 8 + 0] * x10 + s.W2x[c * 8 + 1] * x11 + s.W2x[c * 8 + 2] * x12;
        g_Eg[base] = s.W2x[c * 8 + 3] * x10 + s.W2x[c * 8 + 4] * x11 + s.W2x[c * 8 + 5] * x12;
    }
}

// ---------------------------------------------------------------------------
// Kernel B: stage 1 — 2 free-running teams (named barriers), 512 threads
// grid = BB*GG*2; team t handles s-pair (4p+2t, 4p+2t+1) within its half, 4 passes
// ---------------------------------------------------------------------------
struct SmemB {
    float W11t[64 * WST];
    float W20t[128 * WST];
    float W21t[64 * WST];
    float W1d[64 * 4];
    float Wed[64 * 4];
    float B11[64], B20[64], B21[64];
    float Pf[64 * 16], Pe[64 * 16];     // only this half's 16 s-points, [c][slL]
    float X1h[3 * 16];                  // s-point coords
    float X2[3 * 32];                   // neighbor coords
    float Ha[2][64 * 32], Hb[2][64 * 32];
    float PEa[2][64 * 32], PEb[2][64 * 32];
    float PNa[2][64 * 32], PNb[2][64 * 32];
};

__global__ void __launch_bounds__(512, 1)
kernelB(const float* __restrict__ xyz1, const float* __restrict__ xyz2,
        const float* __restrict__ w10, const float* __restrict__ wx1,
        const float* __restrict__ w11, const float* __restrict__ b11,
        const float* __restrict__ w20, const float* __restrict__ b20,
        const float* __restrict__ w21, const float* __restrict__ b21) {
    extern __shared__ float smem_raw[];
    SmemB& s = *reinterpret_cast<SmemB*>(smem_raw);
    int tid = threadIdx.x;
    int bid = blockIdx.x;
    int b = bid >> 9;
    int g = (bid >> 1) & 255;
    int half = bid & 1;
    int sb = g * MMG;
    int sbh = sb + half * 16;
    long cbase = (long)b * CC * SS;

    for (int idx = tid; idx < 4096; idx += 512) {
        int c = idx >> 6, k = idx & 63;
        s.W11t[k * WST + c] = w11[idx];
        s.W21t[k * WST + c] = w21[idx];
    }
    for (int idx = tid; idx < 8192; idx += 512) {
        int c = idx >> 7, k = idx & 127;
        s.W20t[k * WST + c] = w20[idx];
    }
    if (tid < 256) {
        int c = tid >> 2, j = tid & 3;
        s.W1d[tid] = w10[c * 138 + 6 + j];
        s.Wed[tid] = wx1[c * 10 + 6 + j];
    }
    if (tid < 64) {
        s.B11[tid] = b11[tid];
        s.B20[tid] = b20[tid];
        s.B21[tid] = b21[tid];
    }
    for (int idx = tid; idx < 1024; idx += 512) {
        int c = idx >> 4, sl = idx & 15;
        s.Pf[c * 16 + sl] = g_Pf[cbase + (long)c * SS + sbh + sl];
        s.Pe[c * 16 + sl] = g_Pe[cbase + (long)c * SS + sbh + sl];
    }
    if (tid >= 448 && tid < 496) {
        int i = tid - 448;
        int d = i >> 4, sl = i & 15;
        s.X1h[d * 16 + sl] = xyz1[b * 3 * SS + d * SS + sbh + sl];
    }
    if (tid >= 320 && tid < 416) {
        int i = tid - 320;
        int d = i >> 5, j = i & 31;
        s.X2[d * 32 + j] = xyz2[b * 3 * SS + d * SS + sb + j];
    }
    __syncthreads();

    int lane = tid & 31;
    int wid = tid >> 5;
    int team = wid >> 3;
    int cb = (wid & 7) * 8;
    long outbase = cbase + sb;

    float qf[8], qe[8];
#pragma unroll
    for (int i = 0; i < 8; i++) {
        long base = cbase + (long)(cb + i) * SS + sb + lane;
        qf[i] = __ldg(&g_Qf[base]);
        qe[i] = __ldg(&g_Qe[base]);
    }

    float nx0 = s.X2[lane], nx1 = s.X2[32 + lane], nx2 = s.X2[64 + lane];

    float* Ha = s.Ha[team];  float* Hb = s.Hb[team];
    float* PEa = s.PEa[team]; float* PEb = s.PEb[team];
    float* PNa = s.PNa[team]; float* PNb = s.PNb[team];

    for (int p = 0; p < 4; p++) {
        int slL0 = 4 * p + 2 * team;        // local (0..15)
        int slL1 = slL0 + 1;
        int sl0 = half * 16 + slL0;         // global within group (for output)
        int sl1 = sl0 + 1;

        // --- step 1: dynamic parts for both s ---
        {
            float pa0 = s.X1h[slL0], pa1 = s.X1h[16 + slL0], pa2 = s.X1h[32 + slL0];
            float pb0 = s.X1h[slL1], pb1 = s.X1h[16 + slL1], pb2 = s.X1h[32 + slL1];
            float da0 = nx0 - pa0, da1 = nx1 - pa1, da2 = nx2 - pa2;
            float db0 = nx0 - pb0, db1 = nx1 - pb1, db2 = nx2 - pb2;
            float ea = sqrtf(da0 * da0 + da1 * da1 + da2 * da2 + 1e-20f);
            float eb = sqrtf(db0 * db0 + db1 * db1 + db2 * db2 + 1e-20f);
#pragma unroll
            for (int i = 0; i < 8; i++) {
                int c = cb + i;
                float w0 = s.W1d[c * 4 + 0], w1 = s.W1d[c * 4 + 1], w2 = s.W1d[c * 4 + 2], w3 = s.W1d[c * 4 + 3];
                float ha = s.Pf[c * 16 + slL0] + qf[i] + w0 * da0 + w1 * da1 + w2 * da2 + w3 * ea;
                float hb = s.Pf[c * 16 + slL1] + qf[i] + w0 * db0 + w1 * db1 + w2 * db2 + w3 * eb;
                Ha[c * 32 + lane] = fmaxf(ha, 0.f);
                Hb[c * 32 + lane] = fmaxf(hb, 0.f);
                float v0 = s.Wed[c * 4 + 0], v1 = s.Wed[c * 4 + 1], v2 = s.Wed[c * 4 + 2], v3 = s.Wed[c * 4 + 3];
                float pea = s.Pe[c * 16 + slL0] + qe[i] + v0 * da0 + v1 * da1 + v2 * da2 + v3 * ea;
                float peb = s.Pe[c * 16 + slL1] + qe[i] + v0 * db0 + v1 * db1 + v2 * db2 + v3 * eb;
                PEa[c * 32 + lane] = fmaxf(pea, 0.f);
                PEb[c * 32 + lane] = fmaxf(peb, 0.f);
            }
        }
        TEAM_BAR(team);

        // --- step 2: pi_new = relu(W1_1 @ H + b1_1) ---
        u64 acc0[4], acc1[4];
#pragma unroll
        for (int i = 0; i < 4; i++) {
            u64 bv = *reinterpret_cast<const u64*>(&s.B11[cb + 2 * i]);
            acc0[i] = bv; acc1[i] = bv;
        }
        mmT2(acc0, acc1, s.W11t, cb, Ha, Hb, lane);
#pragma unroll
        for (int i = 0; i < 4; i++) {
            float2 ra = unpack2(acc0[i]), rb = unpack2(acc1[i]);
            PNa[(cb + 2 * i) * 32 + lane] = fmaxf(ra.x, 0.f);
            PNa[(cb + 2 * i + 1) * 32 + lane] = fmaxf(ra.y, 0.f);
            PNb[(cb + 2 * i) * 32 + lane] = fmaxf(rb.x, 0.f);
            PNb[(cb + 2 * i + 1) * 32 + lane] = fmaxf(rb.y, 0.f);
        }
        TEAM_BAR(team);

        // --- step 3: U = relu(W2_0 @ [PE; PN] + b2_0) -> overwrite H ---
#pragma unroll
        for (int i = 0; i < 4; i++) {
            u64 bv = *reinterpret_cast<const u64*>(&s.B20[cb + 2 * i]);
            acc0[i] = bv; acc1[i] = bv;
        }
        mmT2(acc0, acc1, s.W20t, cb, PEa, PEb, lane);
        mmT2(acc0, acc1, s.W20t + 64 * WST, cb, PNa, PNb, lane);
#pragma unroll
        for (int i = 0; i < 4; i++) {
            float2 ra = unpack2(acc0[i]), rb = unpack2(acc1[i]);
            Ha[(cb + 2 * i) * 32 + lane] = fmaxf(ra.x, 0.f);
            Ha[(cb + 2 * i + 1) * 32 + lane] = fmaxf(ra.y, 0.f);
            Hb[(cb + 2 * i) * 32 + lane] = fmaxf(rb.x, 0.f);
            Hb[(cb + 2 * i + 1) * 32 + lane] = fmaxf(rb.y, 0.f);
        }
        TEAM_BAR(team);

        // --- step 4: logits = relu(W2_1 @ U + b2_1); softmax; aggregate ---
#pragma unroll
        for (int i = 0; i < 4; i++) {
            u64 bv = *reinterpret_cast<const u64*>(&s.B21[cb + 2 * i]);
            acc0[i] = bv; acc1[i] = bv;
        }
        mmT2(acc0, acc1, s.W21t, cb, Ha, Hb, lane);
#pragma unroll
        for (int i = 0; i < 4; i++) {
            float2 la = unpack2(acc0[i]), lb = unpack2(acc1[i]);
            int c0 = cb + 2 * i, c1 = c0 + 1;
            float pn00 = PNa[c0 * 32 + lane];
            float pn01 = PNa[c1 * 32 + lane];
            float pn10 = PNb[c0 * 32 + lane];
            float pn11 = PNb[c1 * 32 + lane];
            float e00 = __expf(fmaxf(la.x, 0.f));
            float e01 = __expf(fmaxf(la.y, 0.f));
            float e10 = __expf(fmaxf(lb.x, 0.f));
            float e11 = __expf(fmaxf(lb.y, 0.f));
            float2 r00 = warp_rsum2(e00, e00 * pn00);
            float2 r01 = warp_rsum2(e01, e01 * pn01);
            float2 r10 = warp_rsum2(e10, e10 * pn10);
            float2 r11 = warp_rsum2(e11, e11 * pn11);
            if (lane == 0) {
                g_agg[outbase + (long)c0 * SS + sl0] = r00.y / r00.x;
                g_agg[outbase + (long)c1 * SS + sl0] = r01.y / r01.x;
                g_agg[outbase + (long)c0 * SS + sl1] = r10.y / r10.x;
                g_agg[outbase + (long)c1 * SS + sl1] = r11.y / r11.x;
            }
        }
        TEAM_BAR(team);
    }
}

// ---------------------------------------------------------------------------
// Kernel C: stage 2 — 2 free-running teams (named barriers), 512 threads
// grid = BB*GG*2; hoisted G = W30b @ pi_agg
// ---------------------------------------------------------------------------
struct SmemC {
    float W30at[64 * WST];
    float W30bt[64 * WST];
    float W31t[64 * WST];
    float W2d[64 * 4];
    float B31[64];
    float Eg[64 * 32], PAG[64 * 32];
    float Ef_h[64 * 16], F1_h[64 * 16];     // [c][slL], this half only
    float X1[3 * 32];
    float G[64 * 32];
    float Ta[2][64 * 32], Tb[2][64 * 32];
    float Pa[2][64 * 32], Pb[2][64 * 32];
};

__global__ void __launch_bounds__(512, 1)
kernelC(const float* __restrict__ xyz1, const float* __restrict__ wx2,
        const float* __restrict__ w30, const float* __restrict__ w31,
        const float* __restrict__ b31, float* __restrict__ out) {
    extern __shared__ float smem_raw[];
    SmemC& s = *reinterpret_cast<SmemC*>(smem_raw);
    int tid = threadIdx.x;
    int bid = blockIdx.x;
    int b = bid >> 9;
    int g = (bid >> 1) & 255;
    int half = bid & 1;
    int sb = g * MMG;
    int sbh = sb + half * 16;
    long cbase = (long)b * CC * SS;

    for (int idx = tid; idx < 4096; idx += 512) {
        int c = idx >> 6, k = idx & 63;
        s.W30at[k * WST + c] = w30[c * 192 + k];
        s.W30bt[k * WST + c] = w30[c * 192 + 128 + k];
        s.W31t[k * WST + c] = w31[c * 64 + k];
    }
    if (tid < 256) {
        int c = tid >> 2, j = tid & 3;
        s.W2d[tid] = wx2[c * 10 + 6 + j];
    }
    if (tid < 64) s.B31[tid] = b31[tid];
    for (int idx = tid; idx < 2048; idx += 512) {
        int c = idx >> 5, k = idx & 31;
        long base = cbase + (long)c * SS + sb + k;
        s.Eg[idx] = g_Eg[base];
        s.PAG[idx] = g_agg[base];
    }
    for (int idx = tid; idx < 1024; idx += 512) {
        int c = idx >> 4, sl = idx & 15;
        s.Ef_h[c * 16 + sl] = g_Ef[cbase + (long)c * SS + sbh + sl];
        s.F1_h[c * 16 + sl] = g_F1[cbase + (long)c * SS + sbh + sl];
    }
    if (tid >= 384 && tid < 480) {
        int i = tid - 384;
        int d = i >> 5, k = i & 31;
        s.X1[d * 32 + k] = xyz1[b * 3 * SS + d * SS + sb + k];
    }
    __syncthreads();

    int lane = tid & 31;
    int wid = tid >> 5;
    int team = wid >> 3;
    int cb = (wid & 7) * 8;
    long outbase = cbase + sb;

    // --- G = W30b @ pi_agg (s-independent): 16 warps x 4 channels, shared ---
    {
        int c4 = wid * 4;
        u64 gacc[2] = {0ull, 0ull};
#pragma unroll 8
        for (int k = 0; k < 64; k++) {
            ulonglong2 w = *reinterpret_cast<const ulonglong2*>(s.W30bt + k * WST + c4);
            u64 a = splat2(s.PAG[k * 32 + lane]);
            ffma2(gacc[0], w.x, a);
            ffma2(gacc[1], w.y, a);
        }
        float2 v0 = unpack2(gacc[0]), v1 = unpack2(gacc[1]);
        s.G[(c4 + 0) * 32 + lane] = v0.x;
        s.G[(c4 + 1) * 32 + lane] = v0.y;
        s.G[(c4 + 2) * 32 + lane] = v1.x;
        s.G[(c4 + 3) * 32 + lane] = v1.y;
    }
    __syncthreads();   // G is shared across teams — block-wide sync once

    float nx0 = s.X1[lane], nx1 = s.X1[32 + lane], nx2 = s.X1[64 + lane];

    float* Pa = s.Pa[team]; float* Pb = s.Pb[team];
    float* Ta = s.Ta[team]; float* Tb = s.Tb[team];

    for (int p = 0; p < 4; p++) {
        int slL0 = 4 * p + 2 * team;
        int slL1 = slL0 + 1;
        int sl0 = half * 16 + slL0;
        int sl1 = sl0 + 1;

        // --- step 1: pc_enc for both s ---
        {
            float pa0 = s.X1[sl0], pa1 = s.X1[32 + sl0], pa2 = s.X1[64 + sl0];
            float pb0 = s.X1[sl1], pb1 = s.X1[32 + sl1], pb2 = s.X1[64 + sl1];
            float da0 = nx0 - pa0, da1 = nx1 - pa1, da2 = nx2 - pa2;
            float db0 = nx0 - pb0, db1 = nx1 - pb1, db2 = nx2 - pb2;
            float ea = sqrtf(da0 * da0 + da1 * da1 + da2 * da2 + 1e-20f);
            float eb = sqrtf(db0 * db0 + db1 * db1 + db2 * db2 + 1e-20f);
#pragma unroll
            for (int i = 0; i < 8; i++) {
                int c = cb + i;
                float w0 = s.W2d[c * 4 + 0], w1 = s.W2d[c * 4 + 1], w2 = s.W2d[c * 4 + 2], w3 = s.W2d[c * 4 + 3];
                float base_c = s.Eg[c * 32 + lane];
                float va = s.Ef_h[c * 16 + slL0] + base_c + w0 * da0 + w1 * da1 + w2 * da2 + w3 * ea;
                float vb = s.Ef_h[c * 16 + slL1] + base_c + w0 * db0 + w1 * db1 + w2 * db2 + w3 * eb;
                Pa[c * 32 + lane] = fmaxf(va, 0.f);
                Pb[c * 32 + lane] = fmaxf(vb, 0.f);
            }
        }
        TEAM_BAR(team);

        // --- step 2: T = relu(G + F1[.,sl] + W3_0a @ pc_enc) ---
        u64 acc0[4], acc1[4];
#pragma unroll
        for (int i = 0; i < 4; i++) {
            int c0 = cb + 2 * i, c1 = c0 + 1;
            float g0 = s.G[c0 * 32 + lane], g1 = s.G[c1 * 32 + lane];
            acc0[i] = pack2(g0 + s.F1_h[c0 * 16 + slL0], g1 + s.F1_h[c1 * 16 + slL0]);
            acc1[i] = pack2(g0 + s.F1_h[c0 * 16 + slL1], g1 + s.F1_h[c1 * 16 + slL1]);
        }
        mmT2(acc0, acc1, s.W30at, cb, Pa, Pb, lane);
#pragma unroll
        for (int i = 0; i < 4; i++) {
            float2 ra = unpack2(acc0[i]), rb = unpack2(acc1[i]);
            Ta[(cb + 2 * i) * 32 + lane] = fmaxf(ra.x, 0.f);
            Ta[(cb + 2 * i + 1) * 32 + lane] = fmaxf(ra.y, 0.f);
            Tb[(cb + 2 * i) * 32 + lane] = fmaxf(rb.x, 0.f);
            Tb[(cb + 2 * i + 1) * 32 + lane] = fmaxf(rb.y, 0.f);
        }
        TEAM_BAR(team);

        // --- step 3: logits = relu(W3_1 @ T + b3_1); masked softmax; aggregate ---
#pragma unroll
        for (int i = 0; i < 4; i++) {
            u64 bv = *reinterpret_cast<const u64*>(&s.B31[cb + 2 * i]);
            acc0[i] = bv; acc1[i] = bv;
        }
        mmT2(acc0, acc1, s.W31t, cb, Ta, Tb, lane);
#pragma unroll
        for (int i = 0; i < 4; i++) {
            float2 la = unpack2(acc0[i]), lb = unpack2(acc1[i]);
            int c0 = cb + 2 * i, c1 = c0 + 1;
            float pg0 = s.PAG[c0 * 32 + lane];
            float pg1 = s.PAG[c1 * 32 + lane];
            float e00 = (lane == sl0) ? 0.f : __expf(fmaxf(la.x, 0.f));
            float e01 = (lane == sl0) ? 0.f : __expf(fmaxf(la.y, 0.f));
            float e10 = (lane == sl1) ? 0.f : __expf(fmaxf(lb.x, 0.f));
            float e11 = (lane == sl1) ? 0.f : __expf(fmaxf(lb.y, 0.f));
            float2 r00 = warp_rsum2(e00, e00 * pg0);
            float2 r01 = warp_rsum2(e01, e01 * pg1);
            float2 r10 = warp_rsum2(e10, e10 * pg0);
            float2 r11 = warp_rsum2(e11, e11 * pg1);
            if (lane == 0) {
                out[outbase + (long)c0 * SS + sl0] = r00.y / r00.x;
                out[outbase + (long)c1 * SS + sl0] = r01.y / r01.x;
                out[outbase + (long)c0 * SS + sl1] = r10.y / r10.x;
                out[outbase + (long)c1 * SS + sl1] = r11.y / r11.x;
            }
        }
        TEAM_BAR(team);
    }
}

// ---------------------------------------------------------------------------
extern "C" void kernel_launch(void* const* d_in, const int* in_sizes, int n_in,
                              void* d_out, int out_size) {
    const float* xyz1 = (const float*)d_in[0];
    const float* feat1 = (const float*)d_in[1];
    const float* xyz2 = (const float*)d_in[2];
    const float* feat2 = (const float*)d_in[3];
    const float* w10 = (const float*)d_in[4];
    const float* b10 = (const float*)d_in[5];
    const float* w11 = (const float*)d_in[6];
    const float* b11 = (const float*)d_in[7];
    const float* wx1 = (const float*)d_in[8];
    const float* bx1 = (const float*)d_in[9];
    const float* wx2 = (const float*)d_in[10];
    const float* bx2 = (const float*)d_in[11];
    const float* w20 = (const float*)d_in[12];
    const float* b20 = (const float*)d_in[13];
    const float* w21 = (const float*)d_in[14];
    const float* b21 = (const float*)d_in[15];
    const float* w30 = (const float*)d_in[16];
    const float* b30 = (const float*)d_in[17];
    const float* w31 = (const float*)d_in[18];
    const float* b31 = (const float*)d_in[19];
    float* out = (float*)d_out;

    cudaFuncSetAttribute(kernelA, cudaFuncAttributeMaxDynamicSharedMemorySize, (int)sizeof(SmemA));
    cudaFuncSetAttribute(kernelB, cudaFuncAttributeMaxDynamicSharedMemorySize, (int)sizeof(SmemB));
    cudaFuncSetAttribute(kernelC, cudaFuncAttributeMaxDynamicSharedMemorySize, (int)sizeof(SmemC));

    kernelA<<<(BB * SS) / 32, 256, sizeof(SmemA)>>>(xyz1, feat1, xyz2, feat2,
                                                    w10, b10, wx1, bx1, wx2, bx2, w30, b30);
    kernelB<<<BB * GG * 2, 512, sizeof(SmemB)>>>(xyz1, xyz2, w10, wx1,
                                                 w11, b11, w20, b20, w21, b21);
    kernelC<<<BB * GG * 2, 512, sizeof(SmemC)>>>(xyz1, wx2, w30, w31, b31, out);
}